// round 2
// baseline (speedup 1.0000x reference)
#include <cuda_runtime.h>
#include <math.h>

#define NSTMT 100000
#define NFUNC 50000
#define NTOT  150000
#define TT 16
#define CC 128
#define HH 8
#define DD 16
#define NLAYER 2
#define EE 200000

// ---------------- scratch (static device globals; no allocation) ----------------
__device__ float g_XA[(size_t)NTOT * CC];
__device__ float g_XB[(size_t)NTOT * CC];
__device__ float g_K [(size_t)NTOT * CC];
__device__ float g_Q [(size_t)NTOT * CC];
__device__ float g_V [(size_t)NTOT * CC];
__device__ float g_AGG[(size_t)NTOT * CC];
__device__ float g_KR[(size_t)NSTMT * CC];
__device__ float g_VR[(size_t)NSTMT * CC];
__device__ float g_LG[(size_t)EE * HH];
__device__ float g_M [(size_t)NSTMT * HH];
__device__ float g_S [(size_t)NSTMT * HH];

// ---------------- helpers ----------------
__device__ __forceinline__ void atomicMaxF(float* addr, float v) {
    if (v >= 0.0f) atomicMax((int*)addr, __float_as_int(v));
    else           atomicMin((unsigned int*)addr, __float_as_uint(v));
}

__device__ __forceinline__ void redAdd4(float* p, float4 v) {
    asm volatile("red.global.add.v4.f32 [%0], {%1, %2, %3, %4};"
                 :: "l"(p), "f"(v.x), "f"(v.y), "f"(v.z), "f"(v.w) : "memory");
}

// ---------------- encoder: gather + mean + relu ----------------
// one warp per node; lane covers 4 consecutive channels via float4
__global__ void encode_kernel(const int* __restrict__ tok, const float* __restrict__ emb,
                              float* __restrict__ out, int n)
{
    int node = blockIdx.x * (blockDim.x >> 5) + (threadIdx.x >> 5);
    int lane = threadIdx.x & 31;
    if (node >= n) return;
    const int* tk = tok + (size_t)node * TT;
    float4 acc = make_float4(0.f, 0.f, 0.f, 0.f);
#pragma unroll
    for (int t = 0; t < TT; t++) {
        int id = __ldg(tk + t);
        float4 v = __ldg((const float4*)(emb + (size_t)id * CC) + lane);
        acc.x += v.x; acc.y += v.y; acc.z += v.z; acc.w += v.w;
    }
    const float s = 1.0f / TT;
    acc.x = fmaxf(acc.x * s, 0.f); acc.y = fmaxf(acc.y * s, 0.f);
    acc.z = fmaxf(acc.z * s, 0.f); acc.w = fmaxf(acc.w * s, 0.f);
    ((float4*)(out + (size_t)node * CC))[lane] = acc;
}

// ---------------- GEMM: C[M,128] = act(A[M,128] @ W[128,128] + bias) ----------------
// 128 threads, tile 64 rows x 128 cols, 8x8 register blocking, full K in smem.
__global__ __launch_bounds__(128) void gemm128_kernel(
    const float* __restrict__ A, const float* __restrict__ W,
    const float* __restrict__ bias, float* __restrict__ C, int M, int relu)
{
    extern __shared__ float sm[];
    float* As = sm;                 // [64][132] padded
    float* Ws = sm + 64 * 132;      // [128][128]
    const int tid = threadIdx.x;
    const int tx = tid & 15;        // col group (8 cols each)
    const int ty = tid >> 4;        // row group (8 rows each)
    const int r0 = blockIdx.x * 64;

    // load W (16384 floats)
    const float4* W4 = (const float4*)W;
    float4* Ws4 = (float4*)Ws;
#pragma unroll
    for (int i = 0; i < 32; i++) Ws4[i * 128 + tid] = W4[i * 128 + tid];

    // load A tile (64 x 128), zero-pad tail rows
#pragma unroll
    for (int i = 0; i < 16; i++) {
        int lin = i * 128 + tid;     // 0..2047
        int r = lin >> 5;            // 0..63
        int c4 = lin & 31;           // 0..31 (float4 index)
        float4 v = make_float4(0.f, 0.f, 0.f, 0.f);
        if (r0 + r < M) v = ((const float4*)(A + (size_t)(r0 + r) * CC))[c4];
        float* d = As + r * 132 + c4 * 4;
        d[0] = v.x; d[1] = v.y; d[2] = v.z; d[3] = v.w;
    }
    __syncthreads();

    float acc[8][8];
#pragma unroll
    for (int i = 0; i < 8; i++)
#pragma unroll
        for (int j = 0; j < 8; j++) acc[i][j] = 0.f;

#pragma unroll 8
    for (int k = 0; k < 128; k++) {
        float a[8];
#pragma unroll
        for (int i = 0; i < 8; i++) a[i] = As[(ty * 8 + i) * 132 + k];
        const float4 w0 = ((const float4*)(Ws + k * 128 + tx * 8))[0];
        const float4 w1 = ((const float4*)(Ws + k * 128 + tx * 8))[1];
        float w[8] = {w0.x, w0.y, w0.z, w0.w, w1.x, w1.y, w1.z, w1.w};
#pragma unroll
        for (int i = 0; i < 8; i++)
#pragma unroll
            for (int j = 0; j < 8; j++) acc[i][j] = fmaf(a[i], w[j], acc[i][j]);
    }

    float b[8];
#pragma unroll
    for (int j = 0; j < 8; j++) b[j] = __ldg(bias + tx * 8 + j);
#pragma unroll
    for (int i = 0; i < 8; i++) {
        int row = r0 + ty * 8 + i;
        if (row >= M) break;
        float o[8];
#pragma unroll
        for (int j = 0; j < 8; j++) {
            o[j] = acc[i][j] + b[j];
            if (relu) o[j] = fmaxf(o[j], 0.f);
        }
        float4* cp = (float4*)(C + (size_t)row * CC + tx * 8);
        cp[0] = make_float4(o[0], o[1], o[2], o[3]);
        cp[1] = make_float4(o[4], o[5], o[6], o[7]);
    }
}

// ---------------- per-head DxD transforms: KR = K @ a_rel[h], VR = V @ m_rel[h] ----------------
// thread = (node, head)
__global__ void relmix_kernel(const float* __restrict__ Ksrc, const float* __restrict__ Vsrc,
                              const float* __restrict__ Arel, const float* __restrict__ Mrel,
                              float* __restrict__ KR, float* __restrict__ VR, int n)
{
    __shared__ float sA[HH * 260];
    __shared__ float sM[HH * 260];
    for (int i = threadIdx.x; i < HH * DD * DD; i += blockDim.x) {
        int h = i >> 8, j = i & 255;
        sA[h * 260 + j] = Arel[i];
        sM[h * 260 + j] = Mrel[i];
    }
    __syncthreads();
    int t = blockIdx.x * blockDim.x + threadIdx.x;
    if (t >= n * HH) return;
    int h = t & 7;

    float k[DD], v[DD];
    const float4* kp = (const float4*)(Ksrc + (size_t)t * DD);
    const float4* vp = (const float4*)(Vsrc + (size_t)t * DD);
#pragma unroll
    for (int i = 0; i < 4; i++) {
        float4 kv = kp[i], vv = vp[i];
        k[i * 4 + 0] = kv.x; k[i * 4 + 1] = kv.y; k[i * 4 + 2] = kv.z; k[i * 4 + 3] = kv.w;
        v[i * 4 + 0] = vv.x; v[i * 4 + 1] = vv.y; v[i * 4 + 2] = vv.z; v[i * 4 + 3] = vv.w;
    }
    float ok[DD], ov[DD];
#pragma unroll
    for (int e = 0; e < DD; e++) {
        float sk = 0.f, sv = 0.f;
#pragma unroll
        for (int d = 0; d < DD; d++) {
            sk = fmaf(k[d], sA[h * 260 + d * DD + e], sk);
            sv = fmaf(v[d], sM[h * 260 + d * DD + e], sv);
        }
        ok[e] = sk; ov[e] = sv;
    }
    float4* kro = (float4*)(KR + (size_t)t * DD);
    float4* vro = (float4*)(VR + (size_t)t * DD);
#pragma unroll
    for (int i = 0; i < 4; i++) {
        kro[i] = make_float4(ok[i * 4], ok[i * 4 + 1], ok[i * 4 + 2], ok[i * 4 + 3]);
        vro[i] = make_float4(ov[i * 4], ov[i * 4 + 1], ov[i * 4 + 2], ov[i * 4 + 3]);
    }
}

// ---------------- per-edge logits + running segment max ----------------
// warp per edge; lane quad -> head
__global__ void logits_kernel(const int* __restrict__ src, const int* __restrict__ dst,
                              const float* __restrict__ Qd, const float* __restrict__ KRs,
                              const float* __restrict__ prel, float* __restrict__ LG,
                              float* __restrict__ Mx, int nE)
{
    int e = blockIdx.x * (blockDim.x >> 5) + (threadIdx.x >> 5);
    if (e >= nE) return;
    int lane = threadIdx.x & 31;
    int s = __ldg(src + e), d = __ldg(dst + e);
    float4 q = __ldg((const float4*)(Qd + (size_t)d * CC) + lane);
    float4 k = __ldg((const float4*)(KRs + (size_t)s * CC) + lane);
    float p = q.x * k.x + q.y * k.y + q.z * k.z + q.w * k.w;
    p += __shfl_xor_sync(0xffffffffu, p, 1);
    p += __shfl_xor_sync(0xffffffffu, p, 2);
    if ((lane & 3) == 0) {
        int h = lane >> 2;
        float lg = p * __ldg(prel + h) * 0.25f;   // scale = 1/sqrt(16)
        LG[(size_t)e * HH + h] = lg;
        atomicMaxF(Mx + (size_t)d * HH + h, lg);
    }
}

// ---------------- exp + segment sum ----------------
__global__ void expsum_kernel(const int* __restrict__ dst, float* __restrict__ LG,
                              const float* __restrict__ Mx, float* __restrict__ Sm, int nE)
{
    int i = blockIdx.x * blockDim.x + threadIdx.x;
    if (i >= nE * HH) return;
    int e = i >> 3, h = i & 7;
    int d = __ldg(dst + e);
    float ev = __expf(LG[i] - Mx[(size_t)d * HH + h]);
    LG[i] = ev;
    atomicAdd(Sm + (size_t)d * HH + h, ev);
}

// ---------------- alpha * v_r scatter into agg ----------------
// warp per edge, vector atomics
__global__ void scatter_kernel(const int* __restrict__ src, const int* __restrict__ dst,
                               const float* __restrict__ LG, const float* __restrict__ Sm,
                               const float* __restrict__ VRs, float* __restrict__ AGGd, int nE)
{
    int e = blockIdx.x * (blockDim.x >> 5) + (threadIdx.x >> 5);
    if (e >= nE) return;
    int lane = threadIdx.x & 31;
    int h = lane >> 2;
    int s = __ldg(src + e), d = __ldg(dst + e);
    float a = __ldg(LG + (size_t)e * HH + h) / (__ldg(Sm + (size_t)d * HH + h) + 1e-16f);
    float4 v = __ldg((const float4*)(VRs + (size_t)s * CC) + lane);
    redAdd4((float*)((float4*)(AGGd + (size_t)d * CC) + lane),
            make_float4(v.x * a, v.y * a, v.z * a, v.w * a));
}

// ---------------- elementwise ----------------
__global__ void gelu_kernel(const float* __restrict__ in, float* __restrict__ out, size_t n4)
{
    size_t i = (size_t)blockIdx.x * blockDim.x + threadIdx.x;
    if (i >= n4) return;
    float4 x = ((const float4*)in)[i];
    float* xs = (float*)&x;
#pragma unroll
    for (int j = 0; j < 4; j++) {
        float v = xs[j];
        float c = 0.7978845608028654f * (v + 0.044715f * v * v * v);
        xs[j] = 0.5f * v * (1.0f + tanhf(c));
    }
    ((float4*)out)[i] = x;
}

__global__ void gate_kernel(const float* __restrict__ o, const float* __restrict__ x,
                            const float* __restrict__ skipp, float* __restrict__ out, size_t n4)
{
    size_t i = (size_t)blockIdx.x * blockDim.x + threadIdx.x;
    if (i >= n4) return;
    float g = 1.0f / (1.0f + __expf(-__ldg(skipp)));
    float4 ov = ((const float4*)o)[i];
    float4 xv = ((const float4*)x)[i];
    float4 r;
    r.x = g * ov.x + (1.f - g) * xv.x;
    r.y = g * ov.y + (1.f - g) * xv.y;
    r.z = g * ov.z + (1.f - g) * xv.z;
    r.w = g * ov.w + (1.f - g) * xv.w;
    ((float4*)out)[i] = r;
}

__global__ void fill_neginf_kernel(float* __restrict__ p, int n)
{
    int i = blockIdx.x * blockDim.x + threadIdx.x;
    if (i < n) p[i] = __int_as_float(0xff800000);   // -inf
}

// ---------------- launcher ----------------
extern "C" void kernel_launch(void* const* d_in, const int* in_sizes, int n_in,
                              void* d_out, int out_size)
{
    const int* tok_stmt = (const int*)d_in[0];
    const int* tok_func = (const int*)d_in[1];
    const int* esrc[3] = {(const int*)d_in[2], (const int*)d_in[4], (const int*)d_in[6]};
    const int* edst[3] = {(const int*)d_in[3], (const int*)d_in[5], (const int*)d_in[7]};
    const float* emb   = (const float*)d_in[8];
    const float* lin_w = (const float*)d_in[9];
    const float* lin_b = (const float*)d_in[10];
    const float* kw = (const float*)d_in[11];
    const float* kb = (const float*)d_in[12];
    const float* qw = (const float*)d_in[13];
    const float* qb = (const float*)d_in[14];
    const float* vw = (const float*)d_in[15];
    const float* vb = (const float*)d_in[16];
    const float* aw = (const float*)d_in[17];
    const float* ab = (const float*)d_in[18];
    const float* skip = (const float*)d_in[19];
    const float* a_rel = (const float*)d_in[20];
    const float* m_rel = (const float*)d_in[21];
    const float* p_rel = (const float*)d_in[22];
    float* out = (float*)d_out;

    float *XA, *XB, *K, *Q, *V, *AGG, *KR, *VR, *LG, *Mx, *Sm;
    cudaGetSymbolAddress((void**)&XA, g_XA);
    cudaGetSymbolAddress((void**)&XB, g_XB);
    cudaGetSymbolAddress((void**)&K,  g_K);
    cudaGetSymbolAddress((void**)&Q,  g_Q);
    cudaGetSymbolAddress((void**)&V,  g_V);
    cudaGetSymbolAddress((void**)&AGG, g_AGG);
    cudaGetSymbolAddress((void**)&KR, g_KR);
    cudaGetSymbolAddress((void**)&VR, g_VR);
    cudaGetSymbolAddress((void**)&LG, g_LG);
    cudaGetSymbolAddress((void**)&Mx, g_M);
    cudaGetSymbolAddress((void**)&Sm, g_S);

    const int GEMM_SMEM = (64 * 132 + 128 * 128) * 4;   // 99328 B
    cudaFuncSetAttribute(gemm128_kernel, cudaFuncAttributeMaxDynamicSharedMemorySize, GEMM_SMEM);

    const int Nt[2] = {NSTMT, NFUNC};
    const size_t base[2] = {0, (size_t)NSTMT * CC};

    // ---- encoder ----
    encode_kernel<<<(NSTMT + 7) / 8, 256>>>(tok_stmt, emb, AGG, NSTMT);
    encode_kernel<<<(NFUNC + 7) / 8, 256>>>(tok_func, emb, AGG + base[1], NFUNC);
    for (int t = 0; t < 2; t++)
        gemm128_kernel<<<(Nt[t] + 63) / 64, 128, GEMM_SMEM>>>(
            AGG + base[t], lin_w + (size_t)t * CC * CC, lin_b + (size_t)t * CC,
            XA + base[t], Nt[t], 1);

    float* Xcur = XA;
    float* Xnext = XB;

    for (int l = 0; l < NLAYER; l++) {
        // K/Q/V projections
        for (int t = 0; t < 2; t++) {
            size_t w_off = (size_t)(l * 2 + t) * CC * CC;
            size_t b_off = (size_t)(l * 2 + t) * CC;
            int gb = (Nt[t] + 63) / 64;
            gemm128_kernel<<<gb, 128, GEMM_SMEM>>>(Xcur + base[t], kw + w_off, kb + b_off, K + base[t], Nt[t], 0);
            gemm128_kernel<<<gb, 128, GEMM_SMEM>>>(Xcur + base[t], qw + w_off, qb + b_off, Q + base[t], Nt[t], 0);
            gemm128_kernel<<<gb, 128, GEMM_SMEM>>>(Xcur + base[t], vw + w_off, vb + b_off, V + base[t], Nt[t], 0);
        }
        cudaMemsetAsync(AGG, 0, (size_t)NTOT * CC * sizeof(float));

        for (int r = 0; r < 3; r++) {
            const int st = (r == 2) ? 1 : 0;
            const int dt = (r == 1) ? 1 : 0;
            const int ns = Nt[st], nd = Nt[dt];
            size_t rel_off = (size_t)(l * 3 + r) * HH * DD * DD;

            relmix_kernel<<<(ns * HH + 255) / 256, 256>>>(
                K + base[st], V + base[st], a_rel + rel_off, m_rel + rel_off, KR, VR, ns);

            fill_neginf_kernel<<<(nd * HH + 255) / 256, 256>>>(Mx, nd * HH);
            cudaMemsetAsync(Sm, 0, (size_t)nd * HH * sizeof(float));

            logits_kernel<<<(EE + 7) / 8, 256>>>(
                esrc[r], edst[r], Q + base[dt], KR, p_rel + (size_t)(l * 3 + r) * HH, LG, Mx, EE);
            expsum_kernel<<<(EE * HH + 255) / 256, 256>>>(edst[r], LG, Mx, Sm, EE);
            scatter_kernel<<<(EE + 7) / 8, 256>>>(esrc[r], edst[r], LG, Sm, VR, AGG + base[dt], EE);
        }

        // output: gelu -> proj -> gated skip
        gelu_kernel<<<((NTOT * CC / 4) + 255) / 256, 256>>>(AGG, K, (size_t)NTOT * CC / 4);
        for (int t = 0; t < 2; t++) {
            size_t w_off = (size_t)(l * 2 + t) * CC * CC;
            size_t b_off = (size_t)(l * 2 + t) * CC;
            gemm128_kernel<<<(Nt[t] + 63) / 64, 128, GEMM_SMEM>>>(
                K + base[t], aw + w_off, ab + b_off, Q + base[t], Nt[t], 0);
        }
        float* gate_out = (l == NLAYER - 1) ? out : Xnext;
        for (int t = 0; t < 2; t++) {
            size_t n4 = (size_t)Nt[t] * CC / 4;
            gate_kernel<<<(int)((n4 + 255) / 256), 256>>>(
                Q + base[t], Xcur + base[t], skip + (size_t)(l * 2 + t), gate_out + base[t], n4);
        }
        float* tmp = Xcur; Xcur = Xnext; Xnext = tmp;
    }
}

// round 3
// speedup vs baseline: 1.1122x; 1.1122x over previous
#include <cuda_runtime.h>
#include <math.h>

#define NSTMT 100000
#define NFUNC 50000
#define NTOT  150000
#define TT 16
#define CC 128
#define HH 8
#define DD 16
#define NLAYER 2
#define EE 200000

// ---------------- scratch (static device globals; no allocation) ----------------
__device__ float g_XA[(size_t)NTOT * CC];
__device__ float g_XB[(size_t)NTOT * CC];
__device__ float g_K [(size_t)NTOT * CC];
__device__ float g_Q [(size_t)NTOT * CC];
__device__ float g_V [(size_t)NTOT * CC];
__device__ float g_AGG[(size_t)NTOT * CC];
__device__ float g_KR[(size_t)NSTMT * CC];
__device__ float g_VR[(size_t)NSTMT * CC];
__device__ float g_LG[(size_t)EE * HH];
__device__ float g_M [(size_t)NSTMT * HH];
__device__ float g_S [(size_t)NSTMT * HH];

// ---------------- helpers ----------------
__device__ __forceinline__ void atomicMaxF(float* addr, float v) {
    if (v >= 0.0f) atomicMax((int*)addr, __float_as_int(v));
    else           atomicMin((unsigned int*)addr, __float_as_uint(v));
}

__device__ __forceinline__ void redAdd4(float* p, float4 v) {
    asm volatile("red.global.add.v4.f32 [%0], {%1, %2, %3, %4};"
                 :: "l"(p), "f"(v.x), "f"(v.y), "f"(v.z), "f"(v.w) : "memory");
}

__device__ __forceinline__ unsigned long long packdup(float a) {
    unsigned long long r;
    asm("mov.b64 %0, {%1, %1};" : "=l"(r) : "f"(a));
    return r;
}
__device__ __forceinline__ void fma2(unsigned long long& acc, unsigned long long a, unsigned long long b) {
    asm("fma.rn.f32x2 %0, %1, %2, %0;" : "+l"(acc) : "l"(a), "l"(b));
}
__device__ __forceinline__ void unpack2(unsigned long long v, float& lo, float& hi) {
    asm("mov.b64 {%0, %1}, %2;" : "=f"(lo), "=f"(hi) : "l"(v));
}

// ---------------- encoder: gather + mean + relu ----------------
__global__ void encode_kernel(const int* __restrict__ tok, const float* __restrict__ emb,
                              float* __restrict__ out, int n)
{
    int node = blockIdx.x * (blockDim.x >> 5) + (threadIdx.x >> 5);
    int lane = threadIdx.x & 31;
    if (node >= n) return;
    const int* tk = tok + (size_t)node * TT;
    float4 acc = make_float4(0.f, 0.f, 0.f, 0.f);
#pragma unroll
    for (int t = 0; t < TT; t++) {
        int id = __ldg(tk + t);
        float4 v = __ldg((const float4*)(emb + (size_t)id * CC) + lane);
        acc.x += v.x; acc.y += v.y; acc.z += v.z; acc.w += v.w;
    }
    const float s = 1.0f / TT;
    acc.x = fmaxf(acc.x * s, 0.f); acc.y = fmaxf(acc.y * s, 0.f);
    acc.z = fmaxf(acc.z * s, 0.f); acc.w = fmaxf(acc.w * s, 0.f);
    ((float4*)(out + (size_t)node * CC))[lane] = acc;
}

// ---------------- GEMM v2: C[M,128] = act(A[M,128] @ W[128,128] + bias) ----------------
// tile 128 rows x 64 cols (grid.y = 2), 256 threads, 4x8 outputs/thread,
// packed f32x2 FMAs (FFMA2). A transposed in smem (broadcast a-loads),
// W slice loaded as double2 (pre-paired registers, no packing needed).
__global__ __launch_bounds__(256) void gemm128v2_kernel(
    const float* __restrict__ A, const float* __restrict__ W,
    const float* __restrict__ bias, float* __restrict__ C, int M, int relu)
{
    extern __shared__ float sm[];
    float* At = sm;                  // [128 k][132 pad] transposed
    float* Ws = sm + 128 * 132;      // [128 k][68 pad], 64 cols used
    const int tid = threadIdx.x;
    const int r0 = blockIdx.x * 128;
    const int c0 = blockIdx.y * 64;

    // load W slice: rows k=0..127, cols [c0, c0+64)
#pragma unroll
    for (int i = 0; i < 8; i++) {
        int lin = i * 256 + tid;      // 0..2047
        int k  = lin >> 4;
        int c4 = lin & 15;
        float4 v = __ldg((const float4*)(W + (size_t)k * CC + c0) + c4);
        *(float4*)(Ws + k * 68 + c4 * 4) = v;
    }
    // load A tile transposed: two threads per row (halves of 32 float4)
    {
        int r = tid >> 1;
        int h = (tid & 1) * 16;
        bool ok = (r0 + r) < M;
        const float4* Ap = (const float4*)(A + (size_t)(r0 + r) * CC);
#pragma unroll
        for (int i = 0; i < 16; i++) {
            int c4 = h + i;
            float4 v = ok ? __ldg(Ap + c4) : make_float4(0.f, 0.f, 0.f, 0.f);
            At[(c4 * 4 + 0) * 132 + r] = v.x;
            At[(c4 * 4 + 1) * 132 + r] = v.y;
            At[(c4 * 4 + 2) * 132 + r] = v.z;
            At[(c4 * 4 + 3) * 132 + r] = v.w;
        }
    }
    __syncthreads();

    const int tx = tid & 7;      // cols tx*8 .. tx*8+8 (4 f32x2 pairs)
    const int ty = tid >> 3;     // rows ty*4 .. ty*4+4

    unsigned long long acc[4][4];
#pragma unroll
    for (int i = 0; i < 4; i++)
#pragma unroll
        for (int jp = 0; jp < 4; jp++) acc[i][jp] = 0ull;

#pragma unroll 8
    for (int k = 0; k < 128; k++) {
        float4 av = *(const float4*)(At + k * 132 + ty * 4);
        const double2* wrow = (const double2*)(Ws + k * 68 + tx * 8);
        double2 wa = wrow[0], wb = wrow[1];
        unsigned long long wp[4];
        wp[0] = __double_as_longlong(wa.x);
        wp[1] = __double_as_longlong(wa.y);
        wp[2] = __double_as_longlong(wb.x);
        wp[3] = __double_as_longlong(wb.y);
        unsigned long long ap[4];
        ap[0] = packdup(av.x); ap[1] = packdup(av.y);
        ap[2] = packdup(av.z); ap[3] = packdup(av.w);
#pragma unroll
        for (int i = 0; i < 4; i++)
#pragma unroll
            for (int jp = 0; jp < 4; jp++) fma2(acc[i][jp], ap[i], wp[jp]);
    }

    float b[8];
#pragma unroll
    for (int j = 0; j < 8; j++) b[j] = __ldg(bias + c0 + tx * 8 + j);

#pragma unroll
    for (int i = 0; i < 4; i++) {
        int row = r0 + ty * 4 + i;
        if (row >= M) continue;
        float o[8];
#pragma unroll
        for (int jp = 0; jp < 4; jp++) unpack2(acc[i][jp], o[2 * jp], o[2 * jp + 1]);
#pragma unroll
        for (int j = 0; j < 8; j++) {
            o[j] += b[j];
            if (relu) o[j] = fmaxf(o[j], 0.f);
        }
        float4* cp = (float4*)(C + (size_t)row * CC + c0 + tx * 8);
        cp[0] = make_float4(o[0], o[1], o[2], o[3]);
        cp[1] = make_float4(o[4], o[5], o[6], o[7]);
    }
}

// ---------------- per-head DxD transforms ----------------
__global__ void relmix_kernel(const float* __restrict__ Ksrc, const float* __restrict__ Vsrc,
                              const float* __restrict__ Arel, const float* __restrict__ Mrel,
                              float* __restrict__ KR, float* __restrict__ VR, int n)
{
    __shared__ float sA[HH * 260];
    __shared__ float sM[HH * 260];
    for (int i = threadIdx.x; i < HH * DD * DD; i += blockDim.x) {
        int h = i >> 8, j = i & 255;
        sA[h * 260 + j] = Arel[i];
        sM[h * 260 + j] = Mrel[i];
    }
    __syncthreads();
    int t = blockIdx.x * blockDim.x + threadIdx.x;
    if (t >= n * HH) return;
    int h = t & 7;

    float k[DD], v[DD];
    const float4* kp = (const float4*)(Ksrc + (size_t)t * DD);
    const float4* vp = (const float4*)(Vsrc + (size_t)t * DD);
#pragma unroll
    for (int i = 0; i < 4; i++) {
        float4 kv = kp[i], vv = vp[i];
        k[i * 4 + 0] = kv.x; k[i * 4 + 1] = kv.y; k[i * 4 + 2] = kv.z; k[i * 4 + 3] = kv.w;
        v[i * 4 + 0] = vv.x; v[i * 4 + 1] = vv.y; v[i * 4 + 2] = vv.z; v[i * 4 + 3] = vv.w;
    }
    float ok[DD], ov[DD];
#pragma unroll
    for (int e = 0; e < DD; e++) {
        float sk = 0.f, sv = 0.f;
#pragma unroll
        for (int d = 0; d < DD; d++) {
            sk = fmaf(k[d], sA[h * 260 + d * DD + e], sk);
            sv = fmaf(v[d], sM[h * 260 + d * DD + e], sv);
        }
        ok[e] = sk; ov[e] = sv;
    }
    float4* kro = (float4*)(KR + (size_t)t * DD);
    float4* vro = (float4*)(VR + (size_t)t * DD);
#pragma unroll
    for (int i = 0; i < 4; i++) {
        kro[i] = make_float4(ok[i * 4], ok[i * 4 + 1], ok[i * 4 + 2], ok[i * 4 + 3]);
        vro[i] = make_float4(ov[i * 4], ov[i * 4 + 1], ov[i * 4 + 2], ov[i * 4 + 3]);
    }
}

// ---------------- per-edge logits + running segment max ----------------
__global__ void logits_kernel(const int* __restrict__ src, const int* __restrict__ dst,
                              const float* __restrict__ Qd, const float* __restrict__ KRs,
                              const float* __restrict__ prel, float* __restrict__ LG,
                              float* __restrict__ Mx, int nE)
{
    int e = blockIdx.x * (blockDim.x >> 5) + (threadIdx.x >> 5);
    if (e >= nE) return;
    int lane = threadIdx.x & 31;
    int s = __ldg(src + e), d = __ldg(dst + e);
    float4 q = __ldg((const float4*)(Qd + (size_t)d * CC) + lane);
    float4 k = __ldg((const float4*)(KRs + (size_t)s * CC) + lane);
    float p = q.x * k.x + q.y * k.y + q.z * k.z + q.w * k.w;
    p += __shfl_xor_sync(0xffffffffu, p, 1);
    p += __shfl_xor_sync(0xffffffffu, p, 2);
    if ((lane & 3) == 0) {
        int h = lane >> 2;
        float lg = p * __ldg(prel + h) * 0.25f;   // scale = 1/sqrt(16)
        LG[(size_t)e * HH + h] = lg;
        atomicMaxF(Mx + (size_t)d * HH + h, lg);
    }
}

// ---------------- exp + segment sum ----------------
__global__ void expsum_kernel(const int* __restrict__ dst, float* __restrict__ LG,
                              const float* __restrict__ Mx, float* __restrict__ Sm, int nE)
{
    int i = blockIdx.x * blockDim.x + threadIdx.x;
    if (i >= nE * HH) return;
    int e = i >> 3, h = i & 7;
    int d = __ldg(dst + e);
    float ev = __expf(LG[i] - Mx[(size_t)d * HH + h]);
    LG[i] = ev;
    atomicAdd(Sm + (size_t)d * HH + h, ev);
}

// ---------------- alpha * v_r scatter into agg ----------------
__global__ void scatter_kernel(const int* __restrict__ src, const int* __restrict__ dst,
                               const float* __restrict__ LG, const float* __restrict__ Sm,
                               const float* __restrict__ VRs, float* __restrict__ AGGd, int nE)
{
    int e = blockIdx.x * (blockDim.x >> 5) + (threadIdx.x >> 5);
    if (e >= nE) return;
    int lane = threadIdx.x & 31;
    int h = lane >> 2;
    int s = __ldg(src + e), d = __ldg(dst + e);
    float a = __ldg(LG + (size_t)e * HH + h) / (__ldg(Sm + (size_t)d * HH + h) + 1e-16f);
    float4 v = __ldg((const float4*)(VRs + (size_t)s * CC) + lane);
    redAdd4((float*)((float4*)(AGGd + (size_t)d * CC) + lane),
            make_float4(v.x * a, v.y * a, v.z * a, v.w * a));
}

// ---------------- elementwise ----------------
__global__ void gelu_kernel(const float* __restrict__ in, float* __restrict__ out, size_t n4)
{
    size_t i = (size_t)blockIdx.x * blockDim.x + threadIdx.x;
    if (i >= n4) return;
    float4 x = ((const float4*)in)[i];
    float* xs = (float*)&x;
#pragma unroll
    for (int j = 0; j < 4; j++) {
        float v = xs[j];
        float c = 0.7978845608028654f * (v + 0.044715f * v * v * v);
        xs[j] = 0.5f * v * (1.0f + tanhf(c));
    }
    ((float4*)out)[i] = x;
}

__global__ void gate_kernel(const float* __restrict__ o, const float* __restrict__ x,
                            const float* __restrict__ skipp, float* __restrict__ out, size_t n4)
{
    size_t i = (size_t)blockIdx.x * blockDim.x + threadIdx.x;
    if (i >= n4) return;
    float g = 1.0f / (1.0f + __expf(-__ldg(skipp)));
    float4 ov = ((const float4*)o)[i];
    float4 xv = ((const float4*)x)[i];
    float4 r;
    r.x = g * ov.x + (1.f - g) * xv.x;
    r.y = g * ov.y + (1.f - g) * xv.y;
    r.z = g * ov.z + (1.f - g) * xv.z;
    r.w = g * ov.w + (1.f - g) * xv.w;
    ((float4*)out)[i] = r;
}

__global__ void fill_neginf_kernel(float* __restrict__ p, int n)
{
    int i = blockIdx.x * blockDim.x + threadIdx.x;
    if (i < n) p[i] = __int_as_float(0xff800000);   // -inf
}

// ---------------- launcher ----------------
extern "C" void kernel_launch(void* const* d_in, const int* in_sizes, int n_in,
                              void* d_out, int out_size)
{
    const int* tok_stmt = (const int*)d_in[0];
    const int* tok_func = (const int*)d_in[1];
    const int* esrc[3] = {(const int*)d_in[2], (const int*)d_in[4], (const int*)d_in[6]};
    const int* edst[3] = {(const int*)d_in[3], (const int*)d_in[5], (const int*)d_in[7]};
    const float* emb   = (const float*)d_in[8];
    const float* lin_w = (const float*)d_in[9];
    const float* lin_b = (const float*)d_in[10];
    const float* kw = (const float*)d_in[11];
    const float* kb = (const float*)d_in[12];
    const float* qw = (const float*)d_in[13];
    const float* qb = (const float*)d_in[14];
    const float* vw = (const float*)d_in[15];
    const float* vb = (const float*)d_in[16];
    const float* aw = (const float*)d_in[17];
    const float* ab = (const float*)d_in[18];
    const float* skip = (const float*)d_in[19];
    const float* a_rel = (const float*)d_in[20];
    const float* m_rel = (const float*)d_in[21];
    const float* p_rel = (const float*)d_in[22];
    float* out = (float*)d_out;

    float *XA, *XB, *K, *Q, *V, *AGG, *KR, *VR, *LG, *Mx, *Sm;
    cudaGetSymbolAddress((void**)&XA, g_XA);
    cudaGetSymbolAddress((void**)&XB, g_XB);
    cudaGetSymbolAddress((void**)&K,  g_K);
    cudaGetSymbolAddress((void**)&Q,  g_Q);
    cudaGetSymbolAddress((void**)&V,  g_V);
    cudaGetSymbolAddress((void**)&AGG, g_AGG);
    cudaGetSymbolAddress((void**)&KR, g_KR);
    cudaGetSymbolAddress((void**)&VR, g_VR);
    cudaGetSymbolAddress((void**)&LG, g_LG);
    cudaGetSymbolAddress((void**)&Mx, g_M);
    cudaGetSymbolAddress((void**)&Sm, g_S);

    const int GEMM_SMEM = (128 * 132 + 128 * 68) * 4;   // 102400 B
    cudaFuncSetAttribute(gemm128v2_kernel, cudaFuncAttributeMaxDynamicSharedMemorySize, GEMM_SMEM);

    const int Nt[2] = {NSTMT, NFUNC};
    const size_t base[2] = {0, (size_t)NSTMT * CC};

    // ---- encoder ----
    encode_kernel<<<(NSTMT + 7) / 8, 256>>>(tok_stmt, emb, AGG, NSTMT);
    encode_kernel<<<(NFUNC + 7) / 8, 256>>>(tok_func, emb, AGG + base[1], NFUNC);
    for (int t = 0; t < 2; t++) {
        dim3 g((Nt[t] + 127) / 128, 2);
        gemm128v2_kernel<<<g, 256, GEMM_SMEM>>>(
            AGG + base[t], lin_w + (size_t)t * CC * CC, lin_b + (size_t)t * CC,
            XA + base[t], Nt[t], 1);
    }

    float* Xcur = XA;
    float* Xnext = XB;

    for (int l = 0; l < NLAYER; l++) {
        // K/Q/V projections
        for (int t = 0; t < 2; t++) {
            size_t w_off = (size_t)(l * 2 + t) * CC * CC;
            size_t b_off = (size_t)(l * 2 + t) * CC;
            dim3 g((Nt[t] + 127) / 128, 2);
            gemm128v2_kernel<<<g, 256, GEMM_SMEM>>>(Xcur + base[t], kw + w_off, kb + b_off, K + base[t], Nt[t], 0);
            gemm128v2_kernel<<<g, 256, GEMM_SMEM>>>(Xcur + base[t], qw + w_off, qb + b_off, Q + base[t], Nt[t], 0);
            gemm128v2_kernel<<<g, 256, GEMM_SMEM>>>(Xcur + base[t], vw + w_off, vb + b_off, V + base[t], Nt[t], 0);
        }
        cudaMemsetAsync(AGG, 0, (size_t)NTOT * CC * sizeof(float));

        for (int r = 0; r < 3; r++) {
            const int st = (r == 2) ? 1 : 0;
            const int dt = (r == 1) ? 1 : 0;
            const int ns = Nt[st], nd = Nt[dt];
            size_t rel_off = (size_t)(l * 3 + r) * HH * DD * DD;

            relmix_kernel<<<(ns * HH + 255) / 256, 256>>>(
                K + base[st], V + base[st], a_rel + rel_off, m_rel + rel_off, KR, VR, ns);

            fill_neginf_kernel<<<(nd * HH + 255) / 256, 256>>>(Mx, nd * HH);
            cudaMemsetAsync(Sm, 0, (size_t)nd * HH * sizeof(float));

            logits_kernel<<<(EE + 7) / 8, 256>>>(
                esrc[r], edst[r], Q + base[dt], KR, p_rel + (size_t)(l * 3 + r) * HH, LG, Mx, EE);
            expsum_kernel<<<(EE * HH + 255) / 256, 256>>>(edst[r], LG, Mx, Sm, EE);
            scatter_kernel<<<(EE + 7) / 8, 256>>>(esrc[r], edst[r], LG, Sm, VR, AGG + base[dt], EE);
        }

        // output: gelu -> proj -> gated skip
        gelu_kernel<<<((NTOT * CC / 4) + 255) / 256, 256>>>(AGG, K, (size_t)NTOT * CC / 4);
        for (int t = 0; t < 2; t++) {
            size_t w_off = (size_t)(l * 2 + t) * CC * CC;
            size_t b_off = (size_t)(l * 2 + t) * CC;
            dim3 g((Nt[t] + 127) / 128, 2);
            gemm128v2_kernel<<<g, 256, GEMM_SMEM>>>(
                K + base[t], aw + w_off, ab + b_off, Q + base[t], Nt[t], 0);
        }
        float* gate_out = (l == NLAYER - 1) ? out : Xnext;
        for (int t = 0; t < 2; t++) {
            size_t n4 = (size_t)Nt[t] * CC / 4;
            gate_kernel<<<(int)((n4 + 255) / 256), 256>>>(
                Q + base[t], Xcur + base[t], skip + (size_t)(l * 2 + t), gate_out + base[t], n4);
        }
        float* tmp = Xcur; Xcur = Xnext; Xnext = tmp;
    }
}

// round 4
// speedup vs baseline: 1.1412x; 1.0261x over previous
#include <cuda_runtime.h>
#include <math.h>

#define NSTMT 100000
#define NFUNC 50000
#define NTOT  150000
#define TT 16
#define CC 128
#define HH 8
#define DD 16
#define NLAYER 2
#define EE 200000

// ---------------- scratch (static device globals; no allocation) ----------------
__device__ float g_XA[(size_t)NTOT * CC];
__device__ float g_XB[(size_t)NTOT * CC];
__device__ float g_K [(size_t)NTOT * CC];
__device__ float g_Q [(size_t)NTOT * CC];
__device__ float g_V [(size_t)NTOT * CC];
__device__ float g_AGG[(size_t)NTOT * CC];
__device__ float g_KR[(size_t)NSTMT * CC];
__device__ float g_VR[(size_t)NSTMT * CC];
__device__ float g_LG[(size_t)EE * HH];
__device__ float g_M [(size_t)NSTMT * HH];
__device__ float g_S [(size_t)NSTMT * HH];

// ---------------- helpers ----------------
__device__ __forceinline__ void atomicMaxF(float* addr, float v) {
    if (v >= 0.0f) atomicMax((int*)addr, __float_as_int(v));
    else           atomicMin((unsigned int*)addr, __float_as_uint(v));
}

__device__ __forceinline__ void redAdd4(float* p, float4 v) {
    asm volatile("red.global.add.v4.f32 [%0], {%1, %2, %3, %4};"
                 :: "l"(p), "f"(v.x), "f"(v.y), "f"(v.z), "f"(v.w) : "memory");
}

__device__ __forceinline__ unsigned long long packdup(float a) {
    unsigned long long r;
    asm("mov.b64 %0, {%1, %1};" : "=l"(r) : "f"(a));
    return r;
}
__device__ __forceinline__ void fma2(unsigned long long& acc, unsigned long long a, unsigned long long b) {
    asm("fma.rn.f32x2 %0, %1, %2, %0;" : "+l"(acc) : "l"(a), "l"(b));
}
__device__ __forceinline__ void unpack2(unsigned long long v, float& lo, float& hi) {
    asm("mov.b64 {%0, %1}, %2;" : "=f"(lo), "=f"(hi) : "l"(v));
}

__device__ __forceinline__ float gelu1(float v) {
    float c = 0.7978845608028654f * (v + 0.044715f * v * v * v);
    return 0.5f * v * (1.0f + tanhf(c));
}

// ---------------- encoder: gather + mean + relu ----------------
__global__ void encode_kernel(const int* __restrict__ tok, const float* __restrict__ emb,
                              float* __restrict__ out, int n)
{
    int node = blockIdx.x * (blockDim.x >> 5) + (threadIdx.x >> 5);
    int lane = threadIdx.x & 31;
    if (node >= n) return;
    const int* tk = tok + (size_t)node * TT;
    float4 acc = make_float4(0.f, 0.f, 0.f, 0.f);
#pragma unroll
    for (int t = 0; t < TT; t++) {
        int id = __ldg(tk + t);
        float4 v = __ldg((const float4*)(emb + (size_t)id * CC) + lane);
        acc.x += v.x; acc.y += v.y; acc.z += v.z; acc.w += v.w;
    }
    const float s = 1.0f / TT;
    acc.x = fmaxf(acc.x * s, 0.f); acc.y = fmaxf(acc.y * s, 0.f);
    acc.z = fmaxf(acc.z * s, 0.f); acc.w = fmaxf(acc.w * s, 0.f);
    ((float4*)(out + (size_t)node * CC))[lane] = acc;
}

// ---------------- GEMM v3: C[M,64-slice] = epi(act_in(A)[M,128] @ W[128,128] + bias) ----
// tile 128 rows x 64 cols (grid.y = 2), 256 threads, 4x8 outputs/thread, FFMA2,
// manual register double-buffering of the k+1 fragments.
// flags: bit0 = relu on output, bit1 = gelu on A load.
// Xg/skipp non-null => gated skip epilogue: out = g*o + (1-g)*Xg, g = sigmoid(*skipp).
__global__ __launch_bounds__(256, 2) void gemm128v3_kernel(
    const float* __restrict__ A, const float* __restrict__ W,
    const float* __restrict__ bias, float* __restrict__ C, int M, int flags,
    const float* __restrict__ Xg, const float* __restrict__ skipp)
{
    extern __shared__ float sm[];
    float* At = sm;                  // [128 k][132 pad] transposed
    float* Ws = sm + 128 * 132;      // [128 k][68 pad], 64 cols used
    const int tid = threadIdx.x;
    const int r0 = blockIdx.x * 128;
    const int c0 = blockIdx.y * 64;

    // load W slice: rows k=0..127, cols [c0, c0+64)
#pragma unroll
    for (int i = 0; i < 8; i++) {
        int lin = i * 256 + tid;      // 0..2047
        int k  = lin >> 4;
        int c4 = lin & 15;
        float4 v = __ldg((const float4*)(W + (size_t)k * CC + c0) + c4);
        *(float4*)(Ws + k * 68 + c4 * 4) = v;
    }
    // load A tile transposed (optionally gelu-activated): two threads per row
    {
        int r = tid >> 1;
        int h = (tid & 1) * 16;
        bool ok = (r0 + r) < M;
        const float4* Ap = (const float4*)(A + (size_t)(r0 + r) * CC);
#pragma unroll
        for (int i = 0; i < 16; i++) {
            int c4 = h + i;
            float4 v = ok ? __ldg(Ap + c4) : make_float4(0.f, 0.f, 0.f, 0.f);
            if (flags & 2) {
                v.x = gelu1(v.x); v.y = gelu1(v.y);
                v.z = gelu1(v.z); v.w = gelu1(v.w);
            }
            At[(c4 * 4 + 0) * 132 + r] = v.x;
            At[(c4 * 4 + 1) * 132 + r] = v.y;
            At[(c4 * 4 + 2) * 132 + r] = v.z;
            At[(c4 * 4 + 3) * 132 + r] = v.w;
        }
    }
    __syncthreads();

    const int tx = tid & 7;      // cols tx*8 .. +8 (4 f32x2 pairs)
    const int ty = tid >> 3;     // rows ty*4 .. +4

    unsigned long long acc[4][4];
#pragma unroll
    for (int i = 0; i < 4; i++)
#pragma unroll
        for (int jp = 0; jp < 4; jp++) acc[i][jp] = 0ull;

    // prefetch k = 0
    float4 av = *(const float4*)(At + ty * 4);
    double2 wa = ((const double2*)(Ws + tx * 8))[0];
    double2 wb = ((const double2*)(Ws + tx * 8))[1];

#pragma unroll 4
    for (int k = 0; k < 128; k++) {
        unsigned long long ap0 = packdup(av.x);
        unsigned long long ap1 = packdup(av.y);
        unsigned long long ap2 = packdup(av.z);
        unsigned long long ap3 = packdup(av.w);
        unsigned long long wp0 = __double_as_longlong(wa.x);
        unsigned long long wp1 = __double_as_longlong(wa.y);
        unsigned long long wp2 = __double_as_longlong(wb.x);
        unsigned long long wp3 = __double_as_longlong(wb.y);

        // prefetch k+1 (wraps harmlessly to row 0 on the last iter)
        int kn = (k + 1) & 127;
        av = *(const float4*)(At + kn * 132 + ty * 4);
        wa = ((const double2*)(Ws + kn * 68 + tx * 8))[0];
        wb = ((const double2*)(Ws + kn * 68 + tx * 8))[1];

        fma2(acc[0][0], ap0, wp0); fma2(acc[0][1], ap0, wp1);
        fma2(acc[0][2], ap0, wp2); fma2(acc[0][3], ap0, wp3);
        fma2(acc[1][0], ap1, wp0); fma2(acc[1][1], ap1, wp1);
        fma2(acc[1][2], ap1, wp2); fma2(acc[1][3], ap1, wp3);
        fma2(acc[2][0], ap2, wp0); fma2(acc[2][1], ap2, wp1);
        fma2(acc[2][2], ap2, wp2); fma2(acc[2][3], ap2, wp3);
        fma2(acc[3][0], ap3, wp0); fma2(acc[3][1], ap3, wp1);
        fma2(acc[3][2], ap3, wp2); fma2(acc[3][3], ap3, wp3);
    }

    float b[8];
#pragma unroll
    for (int j = 0; j < 8; j++) b[j] = __ldg(bias + c0 + tx * 8 + j);

    float g = 0.f;
    if (Xg) g = 1.0f / (1.0f + __expf(-__ldg(skipp)));

#pragma unroll
    for (int i = 0; i < 4; i++) {
        int row = r0 + ty * 4 + i;
        if (row >= M) continue;
        float o[8];
#pragma unroll
        for (int jp = 0; jp < 4; jp++) unpack2(acc[i][jp], o[2 * jp], o[2 * jp + 1]);
#pragma unroll
        for (int j = 0; j < 8; j++) {
            o[j] += b[j];
            if (flags & 1) o[j] = fmaxf(o[j], 0.f);
        }
        if (Xg) {
            const float4* xp = (const float4*)(Xg + (size_t)row * CC + c0 + tx * 8);
            float4 x0 = __ldg(xp), x1 = __ldg(xp + 1);
            o[0] = g * o[0] + (1.f - g) * x0.x; o[1] = g * o[1] + (1.f - g) * x0.y;
            o[2] = g * o[2] + (1.f - g) * x0.z; o[3] = g * o[3] + (1.f - g) * x0.w;
            o[4] = g * o[4] + (1.f - g) * x1.x; o[5] = g * o[5] + (1.f - g) * x1.y;
            o[6] = g * o[6] + (1.f - g) * x1.z; o[7] = g * o[7] + (1.f - g) * x1.w;
        }
        float4* cp = (float4*)(C + (size_t)row * CC + c0 + tx * 8);
        cp[0] = make_float4(o[0], o[1], o[2], o[3]);
        cp[1] = make_float4(o[4], o[5], o[6], o[7]);
    }
}

// ---------------- per-head DxD transforms ----------------
__global__ void relmix_kernel(const float* __restrict__ Ksrc, const float* __restrict__ Vsrc,
                              const float* __restrict__ Arel, const float* __restrict__ Mrel,
                              float* __restrict__ KR, float* __restrict__ VR, int n)
{
    __shared__ float sA[HH * 260];
    __shared__ float sM[HH * 260];
    for (int i = threadIdx.x; i < HH * DD * DD; i += blockDim.x) {
        int h = i >> 8, j = i & 255;
        sA[h * 260 + j] = Arel[i];
        sM[h * 260 + j] = Mrel[i];
    }
    __syncthreads();
    int t = blockIdx.x * blockDim.x + threadIdx.x;
    if (t >= n * HH) return;
    int h = t & 7;

    float k[DD], v[DD];
    const float4* kp = (const float4*)(Ksrc + (size_t)t * DD);
    const float4* vp = (const float4*)(Vsrc + (size_t)t * DD);
#pragma unroll
    for (int i = 0; i < 4; i++) {
        float4 kv = kp[i], vv = vp[i];
        k[i * 4 + 0] = kv.x; k[i * 4 + 1] = kv.y; k[i * 4 + 2] = kv.z; k[i * 4 + 3] = kv.w;
        v[i * 4 + 0] = vv.x; v[i * 4 + 1] = vv.y; v[i * 4 + 2] = vv.z; v[i * 4 + 3] = vv.w;
    }
    float ok[DD], ov[DD];
#pragma unroll
    for (int e = 0; e < DD; e++) {
        float sk = 0.f, sv = 0.f;
#pragma unroll
        for (int d = 0; d < DD; d++) {
            sk = fmaf(k[d], sA[h * 260 + d * DD + e], sk);
            sv = fmaf(v[d], sM[h * 260 + d * DD + e], sv);
        }
        ok[e] = sk; ov[e] = sv;
    }
    float4* kro = (float4*)(KR + (size_t)t * DD);
    float4* vro = (float4*)(VR + (size_t)t * DD);
#pragma unroll
    for (int i = 0; i < 4; i++) {
        kro[i] = make_float4(ok[i * 4], ok[i * 4 + 1], ok[i * 4 + 2], ok[i * 4 + 3]);
        vro[i] = make_float4(ov[i * 4], ov[i * 4 + 1], ov[i * 4 + 2], ov[i * 4 + 3]);
    }
}

// ---------------- per-edge logits + running segment max ----------------
__global__ void logits_kernel(const int* __restrict__ src, const int* __restrict__ dst,
                              const float* __restrict__ Qd, const float* __restrict__ KRs,
                              const float* __restrict__ prel, float* __restrict__ LG,
                              float* __restrict__ Mx, int nE)
{
    int e = blockIdx.x * (blockDim.x >> 5) + (threadIdx.x >> 5);
    if (e >= nE) return;
    int lane = threadIdx.x & 31;
    int s = __ldg(src + e), d = __ldg(dst + e);
    float4 q = __ldg((const float4*)(Qd + (size_t)d * CC) + lane);
    float4 k = __ldg((const float4*)(KRs + (size_t)s * CC) + lane);
    float p = q.x * k.x + q.y * k.y + q.z * k.z + q.w * k.w;
    p += __shfl_xor_sync(0xffffffffu, p, 1);
    p += __shfl_xor_sync(0xffffffffu, p, 2);
    if ((lane & 3) == 0) {
        int h = lane >> 2;
        float lg = p * __ldg(prel + h) * 0.25f;   // scale = 1/sqrt(16)
        LG[(size_t)e * HH + h] = lg;
        atomicMaxF(Mx + (size_t)d * HH + h, lg);
    }
}

// ---------------- exp + segment sum ----------------
__global__ void expsum_kernel(const int* __restrict__ dst, float* __restrict__ LG,
                              const float* __restrict__ Mx, float* __restrict__ Sm, int nE)
{
    int i = blockIdx.x * blockDim.x + threadIdx.x;
    if (i >= nE * HH) return;
    int e = i >> 3, h = i & 7;
    int d = __ldg(dst + e);
    float ev = __expf(LG[i] - Mx[(size_t)d * HH + h]);
    LG[i] = ev;
    atomicAdd(Sm + (size_t)d * HH + h, ev);
}

// ---------------- alpha * v_r scatter into agg ----------------
__global__ void scatter_kernel(const int* __restrict__ src, const int* __restrict__ dst,
                               const float* __restrict__ LG, const float* __restrict__ Sm,
                               const float* __restrict__ VRs, float* __restrict__ AGGd, int nE)
{
    int e = blockIdx.x * (blockDim.x >> 5) + (threadIdx.x >> 5);
    if (e >= nE) return;
    int lane = threadIdx.x & 31;
    int h = lane >> 2;
    int s = __ldg(src + e), d = __ldg(dst + e);
    float a = __ldg(LG + (size_t)e * HH + h) / (__ldg(Sm + (size_t)d * HH + h) + 1e-16f);
    float4 v = __ldg((const float4*)(VRs + (size_t)s * CC) + lane);
    redAdd4((float*)((float4*)(AGGd + (size_t)d * CC) + lane),
            make_float4(v.x * a, v.y * a, v.z * a, v.w * a));
}

// ---------------- Mx=-inf, Sm=0 init ----------------
__global__ void init_ms_kernel(float* __restrict__ Mx, float* __restrict__ Sm, int n)
{
    int i = blockIdx.x * blockDim.x + threadIdx.x;
    if (i < n) { Mx[i] = __int_as_float(0xff800000); Sm[i] = 0.f; }
}

// ---------------- launcher ----------------
extern "C" void kernel_launch(void* const* d_in, const int* in_sizes, int n_in,
                              void* d_out, int out_size)
{
    const int* tok_stmt = (const int*)d_in[0];
    const int* tok_func = (const int*)d_in[1];
    const int* esrc[3] = {(const int*)d_in[2], (const int*)d_in[4], (const int*)d_in[6]};
    const int* edst[3] = {(const int*)d_in[3], (const int*)d_in[5], (const int*)d_in[7]};
    const float* emb   = (const float*)d_in[8];
    const float* lin_w = (const float*)d_in[9];
    const float* lin_b = (const float*)d_in[10];
    const float* kw = (const float*)d_in[11];
    const float* kb = (const float*)d_in[12];
    const float* qw = (const float*)d_in[13];
    const float* qb = (const float*)d_in[14];
    const float* vw = (const float*)d_in[15];
    const float* vb = (const float*)d_in[16];
    const float* aw = (const float*)d_in[17];
    const float* ab = (const float*)d_in[18];
    const float* skip = (const float*)d_in[19];
    const float* a_rel = (const float*)d_in[20];
    const float* m_rel = (const float*)d_in[21];
    const float* p_rel = (const float*)d_in[22];
    float* out = (float*)d_out;

    float *XA, *XB, *K, *Q, *V, *AGG, *KR, *VR, *LG, *Mx, *Sm;
    cudaGetSymbolAddress((void**)&XA, g_XA);
    cudaGetSymbolAddress((void**)&XB, g_XB);
    cudaGetSymbolAddress((void**)&K,  g_K);
    cudaGetSymbolAddress((void**)&Q,  g_Q);
    cudaGetSymbolAddress((void**)&V,  g_V);
    cudaGetSymbolAddress((void**)&AGG, g_AGG);
    cudaGetSymbolAddress((void**)&KR, g_KR);
    cudaGetSymbolAddress((void**)&VR, g_VR);
    cudaGetSymbolAddress((void**)&LG, g_LG);
    cudaGetSymbolAddress((void**)&Mx, g_M);
    cudaGetSymbolAddress((void**)&Sm, g_S);

    const int GEMM_SMEM = (128 * 132 + 128 * 68) * 4;   // 102400 B
    cudaFuncSetAttribute(gemm128v3_kernel, cudaFuncAttributeMaxDynamicSharedMemorySize, GEMM_SMEM);

    const int Nt[2] = {NSTMT, NFUNC};
    const size_t base[2] = {0, (size_t)NSTMT * CC};

    // ---- encoder ----
    encode_kernel<<<(NSTMT + 7) / 8, 256>>>(tok_stmt, emb, AGG, NSTMT);
    encode_kernel<<<(NFUNC + 7) / 8, 256>>>(tok_func, emb, AGG + base[1], NFUNC);
    for (int t = 0; t < 2; t++) {
        dim3 g((Nt[t] + 127) / 128, 2);
        gemm128v3_kernel<<<g, 256, GEMM_SMEM>>>(
            AGG + base[t], lin_w + (size_t)t * CC * CC, lin_b + (size_t)t * CC,
            XA + base[t], Nt[t], 1, nullptr, nullptr);
    }

    float* Xcur = XA;
    float* Xnext = XB;

    for (int l = 0; l < NLAYER; l++) {
        // K/Q/V projections
        for (int t = 0; t < 2; t++) {
            size_t w_off = (size_t)(l * 2 + t) * CC * CC;
            size_t b_off = (size_t)(l * 2 + t) * CC;
            dim3 g((Nt[t] + 127) / 128, 2);
            gemm128v3_kernel<<<g, 256, GEMM_SMEM>>>(Xcur + base[t], kw + w_off, kb + b_off, K + base[t], Nt[t], 0, nullptr, nullptr);
            gemm128v3_kernel<<<g, 256, GEMM_SMEM>>>(Xcur + base[t], qw + w_off, qb + b_off, Q + base[t], Nt[t], 0, nullptr, nullptr);
            gemm128v3_kernel<<<g, 256, GEMM_SMEM>>>(Xcur + base[t], vw + w_off, vb + b_off, V + base[t], Nt[t], 0, nullptr, nullptr);
        }
        cudaMemsetAsync(AGG, 0, (size_t)NTOT * CC * sizeof(float));

        for (int r = 0; r < 3; r++) {
            const int st = (r == 2) ? 1 : 0;
            const int dt = (r == 1) ? 1 : 0;
            const int ns = Nt[st], nd = Nt[dt];
            size_t rel_off = (size_t)(l * 3 + r) * HH * DD * DD;

            relmix_kernel<<<(ns * HH + 255) / 256, 256>>>(
                K + base[st], V + base[st], a_rel + rel_off, m_rel + rel_off, KR, VR, ns);

            init_ms_kernel<<<(nd * HH + 255) / 256, 256>>>(Mx, Sm, nd * HH);

            logits_kernel<<<(EE + 7) / 8, 256>>>(
                esrc[r], edst[r], Q + base[dt], KR, p_rel + (size_t)(l * 3 + r) * HH, LG, Mx, EE);
            expsum_kernel<<<(EE * HH + 255) / 256, 256>>>(edst[r], LG, Mx, Sm, EE);
            scatter_kernel<<<(EE + 7) / 8, 256>>>(esrc[r], edst[r], LG, Sm, VR, AGG + base[dt], EE);
        }

        // output: fused gelu(A) -> proj -> gated skip epilogue
        float* gate_out = (l == NLAYER - 1) ? out : Xnext;
        for (int t = 0; t < 2; t++) {
            size_t w_off = (size_t)(l * 2 + t) * CC * CC;
            size_t b_off = (size_t)(l * 2 + t) * CC;
            dim3 g((Nt[t] + 127) / 128, 2);
            gemm128v3_kernel<<<g, 256, GEMM_SMEM>>>(
                AGG + base[t], aw + w_off, ab + b_off, gate_out + base[t], Nt[t], 2,
                Xcur + base[t], skip + (size_t)(l * 2 + t));
        }
        float* tmp = Xcur; Xcur = Xnext; Xnext = tmp;
    }
}

// round 6
// speedup vs baseline: 1.4502x; 1.2707x over previous
#include <cuda_runtime.h>
#include <math.h>

#define NSTMT 100000
#define NFUNC 50000
#define NTOT  150000
#define TT 16
#define CC 128
#define HH 8
#define DD 16
#define NLAYER 2
#define EE 200000

// ---------------- scratch (static device globals; no allocation) ----------------
__device__ float g_XA[(size_t)NTOT * CC];
__device__ float g_XB[(size_t)NTOT * CC];
__device__ float g_K [(size_t)NTOT * CC];
__device__ float g_Q [(size_t)NTOT * CC];
__device__ float g_V [(size_t)NTOT * CC];
__device__ float g_AGG[(size_t)NTOT * CC];
__device__ float g_KR[(size_t)NSTMT * CC];
__device__ float g_VR[(size_t)NSTMT * CC];
__device__ float g_LG[(size_t)EE * HH];
__device__ float g_M [(size_t)NSTMT * HH];
__device__ float g_S [(size_t)NSTMT * HH];

// ---------------- helpers ----------------
__device__ __forceinline__ void atomicMaxF(float* addr, float v) {
    if (v >= 0.0f) atomicMax((int*)addr, __float_as_int(v));
    else           atomicMin((unsigned int*)addr, __float_as_uint(v));
}

__device__ __forceinline__ void redAdd4(float* p, float4 v) {
    asm volatile("red.global.add.v4.f32 [%0], {%1, %2, %3, %4};"
                 :: "l"(p), "f"(v.x), "f"(v.y), "f"(v.z), "f"(v.w) : "memory");
}

__device__ __forceinline__ unsigned long long packdup(float a) {
    unsigned long long r;
    asm("mov.b64 %0, {%1, %1};" : "=l"(r) : "f"(a));
    return r;
}
__device__ __forceinline__ void fma2(unsigned long long& acc, unsigned long long a, unsigned long long b) {
    asm("fma.rn.f32x2 %0, %1, %2, %0;" : "+l"(acc) : "l"(a), "l"(b));
}
__device__ __forceinline__ void unpack2(unsigned long long v, float& lo, float& hi) {
    asm("mov.b64 {%0, %1}, %2;" : "=f"(lo), "=f"(hi) : "l"(v));
}

__device__ __forceinline__ float gelu1(float v) {
    float c = 0.7978845608028654f * (v + 0.044715f * v * v * v);
    return 0.5f * v * (1.0f + tanhf(c));
}

// ---------------- encoder: gather + mean + relu ----------------
__global__ void encode_kernel(const int* __restrict__ tok, const float* __restrict__ emb,
                              float* __restrict__ out, int n)
{
    int node = blockIdx.x * (blockDim.x >> 5) + (threadIdx.x >> 5);
    int lane = threadIdx.x & 31;
    if (node >= n) return;
    const int* tk = tok + (size_t)node * TT;
    float4 acc = make_float4(0.f, 0.f, 0.f, 0.f);
#pragma unroll
    for (int t = 0; t < TT; t++) {
        int id = __ldg(tk + t);
        float4 v = __ldg((const float4*)(emb + (size_t)id * CC) + lane);
        acc.x += v.x; acc.y += v.y; acc.z += v.z; acc.w += v.w;
    }
    const float s = 1.0f / TT;
    acc.x = fmaxf(acc.x * s, 0.f); acc.y = fmaxf(acc.y * s, 0.f);
    acc.z = fmaxf(acc.z * s, 0.f); acc.w = fmaxf(acc.w * s, 0.f);
    ((float4*)(out + (size_t)node * CC))[lane] = acc;
}

// ---------------- GEMM v4: C[M,128] = epi(act_in(A)[M,128] @ W[128,128] + bias) ----
// full 128x128 tile per block, 256 threads, 8x8 outputs/thread, FFMA2.
// 32B a-frag + 32B w-frag feed 32 FFMA2 per k -> fma-pipe bound, not LDS bound.
// flags: bit0 = relu out, bit1 = gelu on A load. Xg/skipp => gated-skip epilogue.
__global__ __launch_bounds__(256) void gemm128v4_kernel(
    const float* __restrict__ A, const float* __restrict__ W,
    const float* __restrict__ bias, float* __restrict__ C, int M, int flags,
    const float* __restrict__ Xg, const float* __restrict__ skipp)
{
    extern __shared__ float sm[];
    float* At = sm;                  // [128 k][132 pad] A transposed
    float* Ws = sm + 128 * 132;      // [128 k][136 pad] W
    const int tid = threadIdx.x;
    const int r0 = blockIdx.x * 128;

    // load W (128x128 = 4096 float4)
#pragma unroll
    for (int i = 0; i < 16; i++) {
        int lin = i * 256 + tid;
        int k  = lin >> 5;
        int c4 = lin & 31;
        float4 v = __ldg((const float4*)(W + (size_t)k * CC) + c4);
        *(float4*)(Ws + k * 136 + c4 * 4) = v;
    }
    // load A tile transposed (optionally gelu)
    {
        int r = tid >> 1;
        int h = (tid & 1) * 16;
        bool ok = (r0 + r) < M;
        const float4* Ap = (const float4*)(A + (size_t)(r0 + r) * CC);
#pragma unroll
        for (int i = 0; i < 16; i++) {
            int c4 = h + i;
            float4 v = ok ? __ldg(Ap + c4) : make_float4(0.f, 0.f, 0.f, 0.f);
            if (flags & 2) {
                v.x = gelu1(v.x); v.y = gelu1(v.y);
                v.z = gelu1(v.z); v.w = gelu1(v.w);
            }
            At[(c4 * 4 + 0) * 132 + r] = v.x;
            At[(c4 * 4 + 1) * 132 + r] = v.y;
            At[(c4 * 4 + 2) * 132 + r] = v.z;
            At[(c4 * 4 + 3) * 132 + r] = v.w;
        }
    }
    __syncthreads();

    const int tx = tid & 15;     // cols tx*8 .. +8 (4 f32x2 pairs)
    const int ty = tid >> 4;     // rows ty*8 .. +8

    unsigned long long acc[8][4];
#pragma unroll
    for (int i = 0; i < 8; i++)
#pragma unroll
        for (int jp = 0; jp < 4; jp++) acc[i][jp] = 0ull;

    // prefetch k = 0
    float4 a0 = *(const float4*)(At + ty * 8);
    float4 a1 = *(const float4*)(At + ty * 8 + 4);
    double2 w0 = ((const double2*)(Ws + tx * 8))[0];
    double2 w1 = ((const double2*)(Ws + tx * 8))[1];

#pragma unroll 2
    for (int k = 0; k < 128; k++) {
        unsigned long long ap[8], wp[4];
        ap[0] = packdup(a0.x); ap[1] = packdup(a0.y);
        ap[2] = packdup(a0.z); ap[3] = packdup(a0.w);
        ap[4] = packdup(a1.x); ap[5] = packdup(a1.y);
        ap[6] = packdup(a1.z); ap[7] = packdup(a1.w);
        wp[0] = __double_as_longlong(w0.x);
        wp[1] = __double_as_longlong(w0.y);
        wp[2] = __double_as_longlong(w1.x);
        wp[3] = __double_as_longlong(w1.y);

        int kn = (k + 1) & 127;
        a0 = *(const float4*)(At + kn * 132 + ty * 8);
        a1 = *(const float4*)(At + kn * 132 + ty * 8 + 4);
        w0 = ((const double2*)(Ws + kn * 136 + tx * 8))[0];
        w1 = ((const double2*)(Ws + kn * 136 + tx * 8))[1];

#pragma unroll
        for (int i = 0; i < 8; i++) {
            fma2(acc[i][0], ap[i], wp[0]);
            fma2(acc[i][1], ap[i], wp[1]);
            fma2(acc[i][2], ap[i], wp[2]);
            fma2(acc[i][3], ap[i], wp[3]);
        }
    }

    float b[8];
#pragma unroll
    for (int j = 0; j < 8; j++) b[j] = __ldg(bias + tx * 8 + j);

    float g = 0.f;
    if (Xg) g = 1.0f / (1.0f + __expf(-__ldg(skipp)));

#pragma unroll
    for (int i = 0; i < 8; i++) {
        int row = r0 + ty * 8 + i;
        if (row >= M) continue;
        float o[8];
#pragma unroll
        for (int jp = 0; jp < 4; jp++) unpack2(acc[i][jp], o[2 * jp], o[2 * jp + 1]);
#pragma unroll
        for (int j = 0; j < 8; j++) {
            o[j] += b[j];
            if (flags & 1) o[j] = fmaxf(o[j], 0.f);
        }
        if (Xg) {
            const float4* xp = (const float4*)(Xg + (size_t)row * CC + tx * 8);
            float4 x0 = __ldg(xp), x1 = __ldg(xp + 1);
            o[0] = g * o[0] + (1.f - g) * x0.x; o[1] = g * o[1] + (1.f - g) * x0.y;
            o[2] = g * o[2] + (1.f - g) * x0.z; o[3] = g * o[3] + (1.f - g) * x0.w;
            o[4] = g * o[4] + (1.f - g) * x1.x; o[5] = g * o[5] + (1.f - g) * x1.y;
            o[6] = g * o[6] + (1.f - g) * x1.z; o[7] = g * o[7] + (1.f - g) * x1.w;
        }
        float4* cp = (float4*)(C + (size_t)row * CC + tx * 8);
        cp[0] = make_float4(o[0], o[1], o[2], o[3]);
        cp[1] = make_float4(o[4], o[5], o[6], o[7]);
    }
}

// ---------------- per-head DxD transforms ----------------
__global__ void relmix_kernel(const float* __restrict__ Ksrc, const float* __restrict__ Vsrc,
                              const float* __restrict__ Arel, const float* __restrict__ Mrel,
                              float* __restrict__ KR, float* __restrict__ VR, int n)
{
    __shared__ float sA[HH * 260];
    __shared__ float sM[HH * 260];
    for (int i = threadIdx.x; i < HH * DD * DD; i += blockDim.x) {
        int h = i >> 8, j = i & 255;
        sA[h * 260 + j] = Arel[i];
        sM[h * 260 + j] = Mrel[i];
    }
    __syncthreads();
    int t = blockIdx.x * blockDim.x + threadIdx.x;
    if (t >= n * HH) return;
    int h = t & 7;

    float k[DD], v[DD];
    const float4* kp = (const float4*)(Ksrc + (size_t)t * DD);
    const float4* vp = (const float4*)(Vsrc + (size_t)t * DD);
#pragma unroll
    for (int i = 0; i < 4; i++) {
        float4 kv = kp[i], vv = vp[i];
        k[i * 4 + 0] = kv.x; k[i * 4 + 1] = kv.y; k[i * 4 + 2] = kv.z; k[i * 4 + 3] = kv.w;
        v[i * 4 + 0] = vv.x; v[i * 4 + 1] = vv.y; v[i * 4 + 2] = vv.z; v[i * 4 + 3] = vv.w;
    }
    float ok[DD], ov[DD];
#pragma unroll
    for (int e = 0; e < DD; e++) {
        float sk = 0.f, sv = 0.f;
#pragma unroll
        for (int d = 0; d < DD; d++) {
            sk = fmaf(k[d], sA[h * 260 + d * DD + e], sk);
            sv = fmaf(v[d], sM[h * 260 + d * DD + e], sv);
        }
        ok[e] = sk; ov[e] = sv;
    }
    float4* kro = (float4*)(KR + (size_t)t * DD);
    float4* vro = (float4*)(VR + (size_t)t * DD);
#pragma unroll
    for (int i = 0; i < 4; i++) {
        kro[i] = make_float4(ok[i * 4], ok[i * 4 + 1], ok[i * 4 + 2], ok[i * 4 + 3]);
        vro[i] = make_float4(ov[i * 4], ov[i * 4 + 1], ov[i * 4 + 2], ov[i * 4 + 3]);
    }
}

// ---------------- per-edge logits + running segment max ----------------
__global__ void logits_kernel(const int* __restrict__ src, const int* __restrict__ dst,
                              const float* __restrict__ Qd, const float* __restrict__ KRs,
                              const float* __restrict__ prel, float* __restrict__ LG,
                              float* __restrict__ Mx, int nE)
{
    int e = blockIdx.x * (blockDim.x >> 5) + (threadIdx.x >> 5);
    if (e >= nE) return;
    int lane = threadIdx.x & 31;
    int s = __ldg(src + e), d = __ldg(dst + e);
    float4 q = __ldg((const float4*)(Qd + (size_t)d * CC) + lane);
    float4 k = __ldg((const float4*)(KRs + (size_t)s * CC) + lane);
    float p = q.x * k.x + q.y * k.y + q.z * k.z + q.w * k.w;
    p += __shfl_xor_sync(0xffffffffu, p, 1);
    p += __shfl_xor_sync(0xffffffffu, p, 2);
    if ((lane & 3) == 0) {
        int h = lane >> 2;
        float lg = p * __ldg(prel + h) * 0.25f;   // scale = 1/sqrt(16)
        LG[(size_t)e * HH + h] = lg;
        atomicMaxF(Mx + (size_t)d * HH + h, lg);
    }
}

// ---------------- exp + segment sum ----------------
__global__ void expsum_kernel(const int* __restrict__ dst, float* __restrict__ LG,
                              const float* __restrict__ Mx, float* __restrict__ Sm, int nE)
{
    int i = blockIdx.x * blockDim.x + threadIdx.x;
    if (i >= nE * HH) return;
    int e = i >> 3, h = i & 7;
    int d = __ldg(dst + e);
    float ev = __expf(LG[i] - Mx[(size_t)d * HH + h]);
    LG[i] = ev;
    atomicAdd(Sm + (size_t)d * HH + h, ev);
}

// ---------------- alpha * v_r scatter into agg ----------------
__global__ void scatter_kernel(const int* __restrict__ src, const int* __restrict__ dst,
                               const float* __restrict__ LG, const float* __restrict__ Sm,
                               const float* __restrict__ VRs, float* __restrict__ AGGd, int nE)
{
    int e = blockIdx.x * (blockDim.x >> 5) + (threadIdx.x >> 5);
    if (e >= nE) return;
    int lane = threadIdx.x & 31;
    int h = lane >> 2;
    int s = __ldg(src + e), d = __ldg(dst + e);
    float a = __ldg(LG + (size_t)e * HH + h) / (__ldg(Sm + (size_t)d * HH + h) + 1e-16f);
    float4 v = __ldg((const float4*)(VRs + (size_t)s * CC) + lane);
    redAdd4((float*)((float4*)(AGGd + (size_t)d * CC) + lane),
            make_float4(v.x * a, v.y * a, v.z * a, v.w * a));
}

// ---------------- Mx=-inf, Sm=0 init ----------------
__global__ void init_ms_kernel(float* __restrict__ Mx, float* __restrict__ Sm, int n)
{
    int i = blockIdx.x * blockDim.x + threadIdx.x;
    if (i < n) { Mx[i] = __int_as_float(0xff800000); Sm[i] = 0.f; }
}

// ---------------- launcher ----------------
extern "C" void kernel_launch(void* const* d_in, const int* in_sizes, int n_in,
                              void* d_out, int out_size)
{
    const int* tok_stmt = (const int*)d_in[0];
    const int* tok_func = (const int*)d_in[1];
    const int* esrc[3] = {(const int*)d_in[2], (const int*)d_in[4], (const int*)d_in[6]};
    const int* edst[3] = {(const int*)d_in[3], (const int*)d_in[5], (const int*)d_in[7]};
    const float* emb   = (const float*)d_in[8];
    const float* lin_w = (const float*)d_in[9];
    const float* lin_b = (const float*)d_in[10];
    const float* kw = (const float*)d_in[11];
    const float* kb = (const float*)d_in[12];
    const float* qw = (const float*)d_in[13];
    const float* qb = (const float*)d_in[14];
    const float* vw = (const float*)d_in[15];
    const float* vb = (const float*)d_in[16];
    const float* aw = (const float*)d_in[17];
    const float* ab = (const float*)d_in[18];
    const float* skip = (const float*)d_in[19];
    const float* a_rel = (const float*)d_in[20];
    const float* m_rel = (const float*)d_in[21];
    const float* p_rel = (const float*)d_in[22];
    float* out = (float*)d_out;

    float *XA, *XB, *K, *Q, *V, *AGG, *KR, *VR, *LG, *Mx, *Sm;
    cudaGetSymbolAddress((void**)&XA, g_XA);
    cudaGetSymbolAddress((void**)&XB, g_XB);
    cudaGetSymbolAddress((void**)&K,  g_K);
    cudaGetSymbolAddress((void**)&Q,  g_Q);
    cudaGetSymbolAddress((void**)&V,  g_V);
    cudaGetSymbolAddress((void**)&AGG, g_AGG);
    cudaGetSymbolAddress((void**)&KR, g_KR);
    cudaGetSymbolAddress((void**)&VR, g_VR);
    cudaGetSymbolAddress((void**)&LG, g_LG);
    cudaGetSymbolAddress((void**)&Mx, g_M);
    cudaGetSymbolAddress((void**)&Sm, g_S);

    const int GEMM_SMEM = (128 * 132 + 128 * 136) * 4;   // 137216 B
    cudaFuncSetAttribute(gemm128v4_kernel, cudaFuncAttributeMaxDynamicSharedMemorySize, GEMM_SMEM);

    const int Nt[2] = {NSTMT, NFUNC};
    const size_t base[2] = {0, (size_t)NSTMT * CC};

    // ---- encoder ----
    encode_kernel<<<(NSTMT + 7) / 8, 256>>>(tok_stmt, emb, AGG, NSTMT);
    encode_kernel<<<(NFUNC + 7) / 8, 256>>>(tok_func, emb, AGG + base[1], NFUNC);
    for (int t = 0; t < 2; t++) {
        int g = (Nt[t] + 127) / 128;
        gemm128v4_kernel<<<g, 256, GEMM_SMEM>>>(
            AGG + base[t], lin_w + (size_t)t * CC * CC, lin_b + (size_t)t * CC,
            XA + base[t], Nt[t], 1, nullptr, nullptr);
    }

    float* Xcur = XA;
    float* Xnext = XB;

    for (int l = 0; l < NLAYER; l++) {
        // K/Q/V projections
        for (int t = 0; t < 2; t++) {
            size_t w_off = (size_t)(l * 2 + t) * CC * CC;
            size_t b_off = (size_t)(l * 2 + t) * CC;
            int g = (Nt[t] + 127) / 128;
            gemm128v4_kernel<<<g, 256, GEMM_SMEM>>>(Xcur + base[t], kw + w_off, kb + b_off, K + base[t], Nt[t], 0, nullptr, nullptr);
            gemm128v4_kernel<<<g, 256, GEMM_SMEM>>>(Xcur + base[t], qw + w_off, qb + b_off, Q + base[t], Nt[t], 0, nullptr, nullptr);
            gemm128v4_kernel<<<g, 256, GEMM_SMEM>>>(Xcur + base[t], vw + w_off, vb + b_off, V + base[t], Nt[t], 0, nullptr, nullptr);
        }
        cudaMemsetAsync(AGG, 0, (size_t)NTOT * CC * sizeof(float));

        for (int r = 0; r < 3; r++) {
            const int st = (r == 2) ? 1 : 0;
            const int dt = (r == 1) ? 1 : 0;
            const int ns = Nt[st], nd = Nt[dt];
            size_t rel_off = (size_t)(l * 3 + r) * HH * DD * DD;

            relmix_kernel<<<(ns * HH + 255) / 256, 256>>>(
                K + base[st], V + base[st], a_rel + rel_off, m_rel + rel_off, KR, VR, ns);

            init_ms_kernel<<<(nd * HH + 255) / 256, 256>>>(Mx, Sm, nd * HH);

            logits_kernel<<<(EE + 7) / 8, 256>>>(
                esrc[r], edst[r], Q + base[dt], KR, p_rel + (size_t)(l * 3 + r) * HH, LG, Mx, EE);
            expsum_kernel<<<(EE * HH + 255) / 256, 256>>>(edst[r], LG, Mx, Sm, EE);
            scatter_kernel<<<(EE + 7) / 8, 256>>>(esrc[r], edst[r], LG, Sm, VR, AGG + base[dt], EE);
        }

        // output: fused gelu(A) -> proj -> gated skip epilogue
        float* gate_out = (l == NLAYER - 1) ? out : Xnext;
        for (int t = 0; t < 2; t++) {
            size_t w_off = (size_t)(l * 2 + t) * CC * CC;
            size_t b_off = (size_t)(l * 2 + t) * CC;
            int g = (Nt[t] + 127) / 128;
            gemm128v4_kernel<<<g, 256, GEMM_SMEM>>>(
                AGG + base[t], aw + w_off, ab + b_off, gate_out + base[t], Nt[t], 2,
                Xcur + base[t], skip + (size_t)(l * 2 + t));
        }
        float* tmp = Xcur; Xcur = Xnext; Xnext = tmp;
    }
}

// round 8
// speedup vs baseline: 1.7737x; 1.2231x over previous
#include <cuda_runtime.h>
#include <cuda_bf16.h>
#include <math.h>
#include <stdint.h>

#define NSTMT 100000
#define NFUNC 50000
#define NTOT  150000
#define TT 16
#define CC 128
#define HH 8
#define DD 16
#define NLAYER 2
#define EE 200000
#define KPAD 136   // bf16 units per smem row (272 B, 16B-aligned, conflict-skewed)

// ---------------- scratch (static device globals; no allocation) ----------------
__device__ float g_XA[(size_t)NTOT * CC];
__device__ float g_XB[(size_t)NTOT * CC];
__device__ float g_K [(size_t)NTOT * CC];
__device__ float g_Q [(size_t)NTOT * CC];
__device__ float g_V [(size_t)NTOT * CC];
__device__ float g_AGG[(size_t)NTOT * CC];
__device__ float g_KR[(size_t)NSTMT * CC];
__device__ float g_VR[(size_t)NSTMT * CC];
__device__ float g_LG[(size_t)EE * HH];
__device__ float g_M [(size_t)NSTMT * HH];
__device__ float g_S [(size_t)NSTMT * HH];

// ---------------- helpers ----------------
__device__ __forceinline__ void atomicMaxF(float* addr, float v) {
    if (v >= 0.0f) atomicMax((int*)addr, __float_as_int(v));
    else           atomicMin((unsigned int*)addr, __float_as_uint(v));
}

__device__ __forceinline__ void redAdd4(float* p, float4 v) {
    asm volatile("red.global.add.v4.f32 [%0], {%1, %2, %3, %4};"
                 :: "l"(p), "f"(v.x), "f"(v.y), "f"(v.z), "f"(v.w) : "memory");
}

__device__ __forceinline__ float gelu1(float v) {
    float c = 0.7978845608028654f * (v + 0.044715f * v * v * v);
    return 0.5f * v * (1.0f + tanhf(c));
}

__device__ __forceinline__ uint32_t bf2pack(float a, float b) {
    __nv_bfloat162 t = __floats2bfloat162_rn(a, b);
    return *reinterpret_cast<uint32_t*>(&t);
}

__device__ __forceinline__ void mma16816(float* c, uint32_t a0, uint32_t a1, uint32_t a2, uint32_t a3,
                                         uint32_t b0, uint32_t b1) {
    asm volatile(
        "mma.sync.aligned.m16n8k16.row.col.f32.bf16.bf16.f32 "
        "{%0,%1,%2,%3}, {%4,%5,%6,%7}, {%8,%9}, {%0,%1,%2,%3};"
        : "+f"(c[0]), "+f"(c[1]), "+f"(c[2]), "+f"(c[3])
        : "r"(a0), "r"(a1), "r"(a2), "r"(a3), "r"(b0), "r"(b1));
}

// ---------------- encoder: gather + mean + relu ----------------
__global__ void encode_kernel(const int* __restrict__ tok, const float* __restrict__ emb,
                              float* __restrict__ out, int n)
{
    int node = blockIdx.x * (blockDim.x >> 5) + (threadIdx.x >> 5);
    int lane = threadIdx.x & 31;
    if (node >= n) return;
    const int* tk = tok + (size_t)node * TT;
    float4 acc = make_float4(0.f, 0.f, 0.f, 0.f);
#pragma unroll
    for (int t = 0; t < TT; t++) {
        int id = __ldg(tk + t);
        float4 v = __ldg((const float4*)(emb + (size_t)id * CC) + lane);
        acc.x += v.x; acc.y += v.y; acc.z += v.z; acc.w += v.w;
    }
    const float s = 1.0f / TT;
    acc.x = fmaxf(acc.x * s, 0.f); acc.y = fmaxf(acc.y * s, 0.f);
    acc.z = fmaxf(acc.z * s, 0.f); acc.w = fmaxf(acc.w * s, 0.f);
    ((float4*)(out + (size_t)node * CC))[lane] = acc;
}

// ---------------- HMMA GEMM: C[M,128] = epi(act_in(A)[M,128] @ W[128,128] + b) ----
// bf16 hi/lo split via mma.sync.m16n8k16 (sm_80+ path; tcgen05 unavailable in this build).
// 256 threads = 8 warps; warp (wm, wn) = (w&1, w>>1) owns 64 rows x 32 cols.
// smem: Ahi/Alo row-major [128][KPAD], Whi/Wlo transposed [n][KPAD].
// flags: bit0 relu out, bit1 gelu on A. Xg/skipp => gated-skip epilogue.
#define SMEM_GM (4 * 128 * KPAD * 2)

__global__ __launch_bounds__(256) void gemm_mma_kernel(
    const float* __restrict__ A, const float* __restrict__ W,
    const float* __restrict__ bias, float* __restrict__ C, int M, int flags,
    const float* __restrict__ Xg, const float* __restrict__ skipp)
{
    extern __shared__ __align__(16) char smem[];
    uint32_t* AH = (uint32_t*)smem;                    // [128][KPAD/2] u32
    uint32_t* AL = AH + 128 * (KPAD / 2);
    uint32_t* WH = AL + 128 * (KPAD / 2);
    uint32_t* WL = WH + 128 * (KPAD / 2);
    const int tid = threadIdx.x;
    const int r0 = blockIdx.x * 128;

    // ---- A tile: 128 rows x 128 k fp32 -> hi/lo bf16 ----
#pragma unroll
    for (int i = 0; i < 8; i++) {
        int c = tid + i * 256;
        int r = c >> 4, kc = c & 15;          // row, 8-k chunk
        float x[8];
        if (r0 + r < M) {
            const float4* ap = (const float4*)(A + (size_t)(r0 + r) * CC + kc * 8);
            float4 v0 = __ldg(ap), v1 = __ldg(ap + 1);
            x[0] = v0.x; x[1] = v0.y; x[2] = v0.z; x[3] = v0.w;
            x[4] = v1.x; x[5] = v1.y; x[6] = v1.z; x[7] = v1.w;
            if (flags & 2) {
#pragma unroll
                for (int j = 0; j < 8; j++) x[j] = gelu1(x[j]);
            }
        } else {
#pragma unroll
            for (int j = 0; j < 8; j++) x[j] = 0.f;
        }
        int base = r * (KPAD / 2) + kc * 4;
#pragma unroll
        for (int p = 0; p < 4; p++) {
            float a0 = x[2 * p], a1 = x[2 * p + 1];
            float h0 = __bfloat162float(__float2bfloat16_rn(a0));
            float h1 = __bfloat162float(__float2bfloat16_rn(a1));
            AH[base + p] = bf2pack(h0, h1);
            AL[base + p] = bf2pack(a0 - h0, a1 - h1);
        }
    }

    // ---- W: gather transposed [n][k] -> hi/lo (lane-contiguous in n => coalesced) ----
#pragma unroll
    for (int i = 0; i < 8; i++) {
        int c = tid + i * 256;
        int n = c & 127, kc = c >> 7;         // col (output), 8-k chunk
        float x[8];
#pragma unroll
        for (int j = 0; j < 8; j++) x[j] = __ldg(W + (size_t)(kc * 8 + j) * CC + n);
        int base = n * (KPAD / 2) + kc * 4;
#pragma unroll
        for (int p = 0; p < 4; p++) {
            float a0 = x[2 * p], a1 = x[2 * p + 1];
            float h0 = __bfloat162float(__float2bfloat16_rn(a0));
            float h1 = __bfloat162float(__float2bfloat16_rn(a1));
            WH[base + p] = bf2pack(h0, h1);
            WL[base + p] = bf2pack(a0 - h0, a1 - h1);
        }
    }
    __syncthreads();

    const int w    = tid >> 5;
    const int lane = tid & 31;
    const int wm   = (w & 1) * 64;    // warp row base
    const int wn   = (w >> 1) * 32;   // warp col base
    const int gr   = lane >> 2;       // group row 0..7
    const int qp   = lane & 3;        // quad pair 0..3

    float cfr[4][4][4];               // [mt][nt][frag]
#pragma unroll
    for (int i = 0; i < 4; i++)
#pragma unroll
        for (int j = 0; j < 4; j++)
#pragma unroll
            for (int q = 0; q < 4; q++) cfr[i][j][q] = 0.f;

#pragma unroll
    for (int p = 0; p < 3; p++) {
        const uint32_t* As = (p < 2) ? AH : AL;
        const uint32_t* Ws = (p == 1) ? WL : WH;
#pragma unroll
        for (int k16 = 0; k16 < 8; k16++) {
            int kb = k16 * 8 + qp;            // u32 col index of this thread's k-pair
            uint32_t b[4][2];
#pragma unroll
            for (int nt = 0; nt < 4; nt++) {
                int n = wn + nt * 8 + gr;
                b[nt][0] = Ws[n * (KPAD / 2) + kb];
                b[nt][1] = Ws[n * (KPAD / 2) + kb + 4];
            }
#pragma unroll
            for (int mt = 0; mt < 4; mt++) {
                int r = wm + mt * 16 + gr;
                uint32_t a0 = As[r * (KPAD / 2) + kb];
                uint32_t a1 = As[(r + 8) * (KPAD / 2) + kb];
                uint32_t a2 = As[r * (KPAD / 2) + kb + 4];
                uint32_t a3 = As[(r + 8) * (KPAD / 2) + kb + 4];
#pragma unroll
                for (int nt = 0; nt < 4; nt++)
                    mma16816(cfr[mt][nt], a0, a1, a2, a3, b[nt][0], b[nt][1]);
            }
        }
    }

    // ---- epilogue ----
    float g = 0.f;
    if (Xg) g = 1.0f / (1.0f + __expf(-__ldg(skipp)));
#pragma unroll
    for (int mt = 0; mt < 4; mt++) {
#pragma unroll
        for (int half = 0; half < 2; half++) {
            int row = r0 + wm + mt * 16 + gr + half * 8;
            if (row >= M) continue;
#pragma unroll
            for (int nt = 0; nt < 4; nt++) {
                int j = wn + nt * 8 + qp * 2;
                float o0 = cfr[mt][nt][half * 2 + 0] + __ldg(bias + j);
                float o1 = cfr[mt][nt][half * 2 + 1] + __ldg(bias + j + 1);
                if (flags & 1) { o0 = fmaxf(o0, 0.f); o1 = fmaxf(o1, 0.f); }
                if (Xg) {
                    const float2 xv = __ldg((const float2*)(Xg + (size_t)row * CC + j));
                    o0 = g * o0 + (1.f - g) * xv.x;
                    o1 = g * o1 + (1.f - g) * xv.y;
                }
                *(float2*)(C + (size_t)row * CC + j) = make_float2(o0, o1);
            }
        }
    }
}

// ---------------- per-head DxD transforms ----------------
__global__ void relmix_kernel(const float* __restrict__ Ksrc, const float* __restrict__ Vsrc,
                              const float* __restrict__ Arel, const float* __restrict__ Mrel,
                              float* __restrict__ KR, float* __restrict__ VR, int n)
{
    __shared__ float sA[HH * 260];
    __shared__ float sM[HH * 260];
    for (int i = threadIdx.x; i < HH * DD * DD; i += blockDim.x) {
        int h = i >> 8, j = i & 255;
        sA[h * 260 + j] = Arel[i];
        sM[h * 260 + j] = Mrel[i];
    }
    __syncthreads();
    int t = blockIdx.x * blockDim.x + threadIdx.x;
    if (t >= n * HH) return;
    int h = t & 7;

    float k[DD], v[DD];
    const float4* kp = (const float4*)(Ksrc + (size_t)t * DD);
    const float4* vp = (const float4*)(Vsrc + (size_t)t * DD);
#pragma unroll
    for (int i = 0; i < 4; i++) {
        float4 kv = kp[i], vv = vp[i];
        k[i * 4 + 0] = kv.x; k[i * 4 + 1] = kv.y; k[i * 4 + 2] = kv.z; k[i * 4 + 3] = kv.w;
        v[i * 4 + 0] = vv.x; v[i * 4 + 1] = vv.y; v[i * 4 + 2] = vv.z; v[i * 4 + 3] = vv.w;
    }
    float ok[DD], ov[DD];
#pragma unroll
    for (int e = 0; e < DD; e++) {
        float sk = 0.f, sv = 0.f;
#pragma unroll
        for (int d = 0; d < DD; d++) {
            sk = fmaf(k[d], sA[h * 260 + d * DD + e], sk);
            sv = fmaf(v[d], sM[h * 260 + d * DD + e], sv);
        }
        ok[e] = sk; ov[e] = sv;
    }
    float4* kro = (float4*)(KR + (size_t)t * DD);
    float4* vro = (float4*)(VR + (size_t)t * DD);
#pragma unroll
    for (int i = 0; i < 4; i++) {
        kro[i] = make_float4(ok[i * 4], ok[i * 4 + 1], ok[i * 4 + 2], ok[i * 4 + 3]);
        vro[i] = make_float4(ov[i * 4], ov[i * 4 + 1], ov[i * 4 + 2], ov[i * 4 + 3]);
    }
}

// ---------------- per-edge logits + running segment max ----------------
__global__ void logits_kernel(const int* __restrict__ src, const int* __restrict__ dst,
                              const float* __restrict__ Qd, const float* __restrict__ KRs,
                              const float* __restrict__ prel, float* __restrict__ LG,
                              float* __restrict__ Mx, int nE)
{
    int e = blockIdx.x * (blockDim.x >> 5) + (threadIdx.x >> 5);
    if (e >= nE) return;
    int lane = threadIdx.x & 31;
    int s = __ldg(src + e), d = __ldg(dst + e);
    float4 q = __ldg((const float4*)(Qd + (size_t)d * CC) + lane);
    float4 k = __ldg((const float4*)(KRs + (size_t)s * CC) + lane);
    float p = q.x * k.x + q.y * k.y + q.z * k.z + q.w * k.w;
    p += __shfl_xor_sync(0xffffffffu, p, 1);
    p += __shfl_xor_sync(0xffffffffu, p, 2);
    if ((lane & 3) == 0) {
        int h = lane >> 2;
        float lg = p * __ldg(prel + h) * 0.25f;   // scale = 1/sqrt(16)
        LG[(size_t)e * HH + h] = lg;
        atomicMaxF(Mx + (size_t)d * HH + h, lg);
    }
}

// ---------------- exp + segment sum ----------------
__global__ void expsum_kernel(const int* __restrict__ dst, float* __restrict__ LG,
                              const float* __restrict__ Mx, float* __restrict__ Sm, int nE)
{
    int i = blockIdx.x * blockDim.x + threadIdx.x;
    if (i >= nE * HH) return;
    int e = i >> 3, h = i & 7;
    int d = __ldg(dst + e);
    float ev = __expf(LG[i] - Mx[(size_t)d * HH + h]);
    LG[i] = ev;
    atomicAdd(Sm + (size_t)d * HH + h, ev);
}

// ---------------- alpha * v_r scatter into agg ----------------
__global__ void scatter_kernel(const int* __restrict__ src, const int* __restrict__ dst,
                               const float* __restrict__ LG, const float* __restrict__ Sm,
                               const float* __restrict__ VRs, float* __restrict__ AGGd, int nE)
{
    int e = blockIdx.x * (blockDim.x >> 5) + (threadIdx.x >> 5);
    if (e >= nE) return;
    int lane = threadIdx.x & 31;
    int h = lane >> 2;
    int s = __ldg(src + e), d = __ldg(dst + e);
    float a = __ldg(LG + (size_t)e * HH + h) / (__ldg(Sm + (size_t)d * HH + h) + 1e-16f);
    float4 v = __ldg((const float4*)(VRs + (size_t)s * CC) + lane);
    redAdd4((float*)((float4*)(AGGd + (size_t)d * CC) + lane),
            make_float4(v.x * a, v.y * a, v.z * a, v.w * a));
}

// ---------------- Mx=-inf, Sm=0 init ----------------
__global__ void init_ms_kernel(float* __restrict__ Mx, float* __restrict__ Sm, int n)
{
    int i = blockIdx.x * blockDim.x + threadIdx.x;
    if (i < n) { Mx[i] = __int_as_float(0xff800000); Sm[i] = 0.f; }
}

// ---------------- launcher ----------------
extern "C" void kernel_launch(void* const* d_in, const int* in_sizes, int n_in,
                              void* d_out, int out_size)
{
    const int* tok_stmt = (const int*)d_in[0];
    const int* tok_func = (const int*)d_in[1];
    const int* esrc[3] = {(const int*)d_in[2], (const int*)d_in[4], (const int*)d_in[6]};
    const int* edst[3] = {(const int*)d_in[3], (const int*)d_in[5], (const int*)d_in[7]};
    const float* emb   = (const float*)d_in[8];
    const float* lin_w = (const float*)d_in[9];
    const float* lin_b = (const float*)d_in[10];
    const float* kw = (const float*)d_in[11];
    const float* kb = (const float*)d_in[12];
    const float* qw = (const float*)d_in[13];
    const float* qb = (const float*)d_in[14];
    const float* vw = (const float*)d_in[15];
    const float* vb = (const float*)d_in[16];
    const float* aw = (const float*)d_in[17];
    const float* ab = (const float*)d_in[18];
    const float* skip = (const float*)d_in[19];
    const float* a_rel = (const float*)d_in[20];
    const float* m_rel = (const float*)d_in[21];
    const float* p_rel = (const float*)d_in[22];
    float* out = (float*)d_out;

    float *XA, *XB, *K, *Q, *V, *AGG, *KR, *VR, *LG, *Mx, *Sm;
    cudaGetSymbolAddress((void**)&XA, g_XA);
    cudaGetSymbolAddress((void**)&XB, g_XB);
    cudaGetSymbolAddress((void**)&K,  g_K);
    cudaGetSymbolAddress((void**)&Q,  g_Q);
    cudaGetSymbolAddress((void**)&V,  g_V);
    cudaGetSymbolAddress((void**)&AGG, g_AGG);
    cudaGetSymbolAddress((void**)&KR, g_KR);
    cudaGetSymbolAddress((void**)&VR, g_VR);
    cudaGetSymbolAddress((void**)&LG, g_LG);
    cudaGetSymbolAddress((void**)&Mx, g_M);
    cudaGetSymbolAddress((void**)&Sm, g_S);

    cudaFuncSetAttribute(gemm_mma_kernel, cudaFuncAttributeMaxDynamicSharedMemorySize, SMEM_GM);

    const int Nt[2] = {NSTMT, NFUNC};
    const size_t base[2] = {0, (size_t)NSTMT * CC};

    // ---- encoder ----
    encode_kernel<<<(NSTMT + 7) / 8, 256>>>(tok_stmt, emb, AGG, NSTMT);
    encode_kernel<<<(NFUNC + 7) / 8, 256>>>(tok_func, emb, AGG + base[1], NFUNC);
    for (int t = 0; t < 2; t++) {
        int g = (Nt[t] + 127) / 128;
        gemm_mma_kernel<<<g, 256, SMEM_GM>>>(
            AGG + base[t], lin_w + (size_t)t * CC * CC, lin_b + (size_t)t * CC,
            XA + base[t], Nt[t], 1, nullptr, nullptr);
    }

    float* Xcur = XA;
    float* Xnext = XB;

    for (int l = 0; l < NLAYER; l++) {
        // K/Q/V projections
        for (int t = 0; t < 2; t++) {
            size_t w_off = (size_t)(l * 2 + t) * CC * CC;
            size_t b_off = (size_t)(l * 2 + t) * CC;
            int g = (Nt[t] + 127) / 128;
            gemm_mma_kernel<<<g, 256, SMEM_GM>>>(Xcur + base[t], kw + w_off, kb + b_off, K + base[t], Nt[t], 0, nullptr, nullptr);
            gemm_mma_kernel<<<g, 256, SMEM_GM>>>(Xcur + base[t], qw + w_off, qb + b_off, Q + base[t], Nt[t], 0, nullptr, nullptr);
            gemm_mma_kernel<<<g, 256, SMEM_GM>>>(Xcur + base[t], vw + w_off, vb + b_off, V + base[t], Nt[t], 0, nullptr, nullptr);
        }
        cudaMemsetAsync(AGG, 0, (size_t)NTOT * CC * sizeof(float));

        for (int r = 0; r < 3; r++) {
            const int st = (r == 2) ? 1 : 0;
            const int dt = (r == 1) ? 1 : 0;
            const int ns = Nt[st], nd = Nt[dt];
            size_t rel_off = (size_t)(l * 3 + r) * HH * DD * DD;

            relmix_kernel<<<(ns * HH + 255) / 256, 256>>>(
                K + base[st], V + base[st], a_rel + rel_off, m_rel + rel_off, KR, VR, ns);

            init_ms_kernel<<<(nd * HH + 255) / 256, 256>>>(Mx, Sm, nd * HH);

            logits_kernel<<<(EE + 7) / 8, 256>>>(
                esrc[r], edst[r], Q + base[dt], KR, p_rel + (size_t)(l * 3 + r) * HH, LG, Mx, EE);
            expsum_kernel<<<(EE * HH + 255) / 256, 256>>>(edst[r], LG, Mx, Sm, EE);
            scatter_kernel<<<(EE + 7) / 8, 256>>>(esrc[r], edst[r], LG, Sm, VR, AGG + base[dt], EE);
        }

        // output: fused gelu(A) -> proj -> gated skip epilogue
        float* gate_out = (l == NLAYER - 1) ? out : Xnext;
        for (int t = 0; t < 2; t++) {
            size_t w_off = (size_t)(l * 2 + t) * CC * CC;
            size_t b_off = (size_t)(l * 2 + t) * CC;
            int g = (Nt[t] + 127) / 128;
            gemm_mma_kernel<<<g, 256, SMEM_GM>>>(
                AGG + base[t], aw + w_off, ab + b_off, gate_out + base[t], Nt[t], 2,
                Xcur + base[t], skip + (size_t)(l * 2 + t));
        }
        float* tmp = Xcur; Xcur = Xnext; Xnext = tmp;
    }
}

// round 9
// speedup vs baseline: 2.1566x; 1.2159x over previous
#include <cuda_runtime.h>
#include <cuda_bf16.h>
#include <math.h>
#include <stdint.h>

#define NSTMT 100000
#define NFUNC 50000
#define NTOT  150000
#define TT 16
#define CC 128
#define HH 8
#define DD 16
#define NLAYER 2
#define EE 200000
#define KPAD 136   // bf16 units per smem row (272 B, 16B-aligned, conflict-skewed)

// ---------------- scratch (static device globals; no allocation) ----------------
__device__ float g_XA[(size_t)NTOT * CC];
__device__ float g_XB[(size_t)NTOT * CC];
__device__ float g_Q [(size_t)NTOT * CC];
__device__ float g_AGG[(size_t)NTOT * CC];
__device__ float g_KR0[(size_t)NSTMT * CC];
__device__ float g_VR0[(size_t)NSTMT * CC];
__device__ float g_KR1[(size_t)NSTMT * CC];
__device__ float g_VR1[(size_t)NSTMT * CC];
__device__ float g_KR2[(size_t)NFUNC * CC];
__device__ float g_VR2[(size_t)NFUNC * CC];
__device__ float g_LG[(size_t)EE * HH];
__device__ float g_M [(size_t)NSTMT * HH];
__device__ float g_S [(size_t)NSTMT * HH];
// combined rel-folded weights/biases
__device__ float g_WK[(size_t)NLAYER * 3 * CC * CC];
__device__ float g_WV[(size_t)NLAYER * 3 * CC * CC];
__device__ float g_BK[(size_t)NLAYER * 3 * CC];
__device__ float g_BV[(size_t)NLAYER * 3 * CC];

// ---------------- helpers ----------------
__device__ __forceinline__ void atomicMaxF(float* addr, float v) {
    if (v >= 0.0f) atomicMax((int*)addr, __float_as_int(v));
    else           atomicMin((unsigned int*)addr, __float_as_uint(v));
}

__device__ __forceinline__ void redAdd4(float* p, float4 v) {
    asm volatile("red.global.add.v4.f32 [%0], {%1, %2, %3, %4};"
                 :: "l"(p), "f"(v.x), "f"(v.y), "f"(v.z), "f"(v.w) : "memory");
}

__device__ __forceinline__ float gelu1(float v) {
    float c = 0.7978845608028654f * (v + 0.044715f * v * v * v);
    return 0.5f * v * (1.0f + tanhf(c));
}

__device__ __forceinline__ uint32_t bf2pack(float a, float b) {
    __nv_bfloat162 t = __floats2bfloat162_rn(a, b);
    return *reinterpret_cast<uint32_t*>(&t);
}

__device__ __forceinline__ void mma16816(float* c, uint32_t a0, uint32_t a1, uint32_t a2, uint32_t a3,
                                         uint32_t b0, uint32_t b1) {
    asm volatile(
        "mma.sync.aligned.m16n8k16.row.col.f32.bf16.bf16.f32 "
        "{%0,%1,%2,%3}, {%4,%5,%6,%7}, {%8,%9}, {%0,%1,%2,%3};"
        : "+f"(c[0]), "+f"(c[1]), "+f"(c[2]), "+f"(c[3])
        : "r"(a0), "r"(a1), "r"(a2), "r"(a3), "r"(b0), "r"(b1));
}

// ---------------- weight combine: W' = W @ blockdiag(rel), b' = b @ blockdiag(rel) ----
__global__ void combine_kernel(const float* __restrict__ kw, const float* __restrict__ kb,
                               const float* __restrict__ vw, const float* __restrict__ vb,
                               const float* __restrict__ a_rel, const float* __restrict__ m_rel,
                               float* __restrict__ WK, float* __restrict__ BK,
                               float* __restrict__ WV, float* __restrict__ BV)
{
    int b = blockIdx.x;                    // l*6 + r*2 + kind
    int l = b / 6, rr = (b % 6) >> 1, kind = b & 1;
    int st = (rr == 2) ? 1 : 0;
    const float* Wsrc = (kind ? vw : kw) + (size_t)(l * 2 + st) * CC * CC;
    const float* bsrc = (kind ? vb : kb) + (size_t)(l * 2 + st) * CC;
    const float* rel  = (kind ? m_rel : a_rel) + (size_t)(l * 3 + rr) * HH * DD * DD;
    float* Wdst = (kind ? WV : WK) + (size_t)(l * 3 + rr) * CC * CC;
    float* bdst = (kind ? BV : BK) + (size_t)(l * 3 + rr) * CC;

    __shared__ float srel[HH * DD * DD];
    for (int i = threadIdx.x; i < HH * DD * DD; i += blockDim.x) srel[i] = rel[i];
    __syncthreads();

    for (int idx = threadIdx.x; idx < CC * CC; idx += blockDim.x) {
        int j = idx >> 7, c = idx & 127;
        int h = c >> 4, e = c & 15;
        float s = 0.f;
#pragma unroll
        for (int d = 0; d < DD; d++)
            s = fmaf(__ldg(Wsrc + j * CC + h * DD + d), srel[h * DD * DD + d * DD + e], s);
        Wdst[idx] = s;
    }
    if (threadIdx.x < CC) {
        int c = threadIdx.x, h = c >> 4, e = c & 15;
        float s = 0.f;
#pragma unroll
        for (int d = 0; d < DD; d++)
            s = fmaf(__ldg(bsrc + h * DD + d), srel[h * DD * DD + d * DD + e], s);
        bdst[c] = s;
    }
}

// ---------------- encoder: gather + mean + relu ----------------
__global__ void encode_kernel(const int* __restrict__ tok, const float* __restrict__ emb,
                              float* __restrict__ out, int n)
{
    int node = blockIdx.x * (blockDim.x >> 5) + (threadIdx.x >> 5);
    int lane = threadIdx.x & 31;
    if (node >= n) return;
    const int* tk = tok + (size_t)node * TT;
    float4 acc = make_float4(0.f, 0.f, 0.f, 0.f);
#pragma unroll
    for (int t = 0; t < TT; t++) {
        int id = __ldg(tk + t);
        float4 v = __ldg((const float4*)(emb + (size_t)id * CC) + lane);
        acc.x += v.x; acc.y += v.y; acc.z += v.z; acc.w += v.w;
    }
    const float s = 1.0f / TT;
    acc.x = fmaxf(acc.x * s, 0.f); acc.y = fmaxf(acc.y * s, 0.f);
    acc.z = fmaxf(acc.z * s, 0.f); acc.w = fmaxf(acc.w * s, 0.f);
    ((float4*)(out + (size_t)node * CC))[lane] = acc;
}

// ================= HMMA GEMM core pieces (hi/lo split bf16) =================
#define SMEM_GM (4 * 128 * KPAD * 2)

// convert W (gather transposed [n][k]) into WH/WL smem
__device__ __forceinline__ void convert_W(const float* __restrict__ W, uint32_t* WH, uint32_t* WL, int tid)
{
#pragma unroll
    for (int i = 0; i < 8; i++) {
        int c = tid + i * 256;
        int n = c & 127, kc = c >> 7;
        float x[8];
#pragma unroll
        for (int j = 0; j < 8; j++) x[j] = __ldg(W + (size_t)(kc * 8 + j) * CC + n);
        int base = n * (KPAD / 2) + kc * 4;
#pragma unroll
        for (int p = 0; p < 4; p++) {
            float a0 = x[2 * p], a1 = x[2 * p + 1];
            float h0 = __bfloat162float(__float2bfloat16_rn(a0));
            float h1 = __bfloat162float(__float2bfloat16_rn(a1));
            WH[base + p] = bf2pack(h0, h1);
            WL[base + p] = bf2pack(a0 - h0, a1 - h1);
        }
    }
}

// convert A tile (rows r0..r0+127) into AH/AL smem; optional gelu
__device__ __forceinline__ void convert_A(const float* __restrict__ A, uint32_t* AH, uint32_t* AL,
                                          int r0, int M, int tid, bool dogelu)
{
#pragma unroll
    for (int i = 0; i < 8; i++) {
        int c = tid + i * 256;
        int r = c >> 4, kc = c & 15;
        float x[8];
        if (r0 + r < M) {
            const float4* ap = (const float4*)(A + (size_t)(r0 + r) * CC + kc * 8);
            float4 v0 = __ldg(ap), v1 = __ldg(ap + 1);
            x[0] = v0.x; x[1] = v0.y; x[2] = v0.z; x[3] = v0.w;
            x[4] = v1.x; x[5] = v1.y; x[6] = v1.z; x[7] = v1.w;
            if (dogelu) {
#pragma unroll
                for (int j = 0; j < 8; j++) x[j] = gelu1(x[j]);
            }
        } else {
#pragma unroll
            for (int j = 0; j < 8; j++) x[j] = 0.f;
        }
        int base = r * (KPAD / 2) + kc * 4;
#pragma unroll
        for (int p = 0; p < 4; p++) {
            float a0 = x[2 * p], a1 = x[2 * p + 1];
            float h0 = __bfloat162float(__float2bfloat16_rn(a0));
            float h1 = __bfloat162float(__float2bfloat16_rn(a1));
            AH[base + p] = bf2pack(h0, h1);
            AL[base + p] = bf2pack(a0 - h0, a1 - h1);
        }
    }
}

// 3-pass split MMA: cfr += Ahi*Whi + Ahi*Wlo + Alo*Whi
__device__ __forceinline__ void mma_core(const uint32_t* AH, const uint32_t* AL,
                                         const uint32_t* WH, const uint32_t* WL,
                                         int wm, int wn, int gr, int qp, float cfr[4][4][4])
{
#pragma unroll
    for (int i = 0; i < 4; i++)
#pragma unroll
        for (int j = 0; j < 4; j++)
#pragma unroll
            for (int q = 0; q < 4; q++) cfr[i][j][q] = 0.f;
#pragma unroll
    for (int p = 0; p < 3; p++) {
        const uint32_t* As = (p < 2) ? AH : AL;
        const uint32_t* Ws = (p == 1) ? WL : WH;
#pragma unroll
        for (int k16 = 0; k16 < 8; k16++) {
            int kb = k16 * 8 + qp;
            uint32_t b[4][2];
#pragma unroll
            for (int nt = 0; nt < 4; nt++) {
                int n = wn + nt * 8 + gr;
                b[nt][0] = Ws[n * (KPAD / 2) + kb];
                b[nt][1] = Ws[n * (KPAD / 2) + kb + 4];
            }
#pragma unroll
            for (int mt = 0; mt < 4; mt++) {
                int r = wm + mt * 16 + gr;
                uint32_t a0 = As[r * (KPAD / 2) + kb];
                uint32_t a1 = As[(r + 8) * (KPAD / 2) + kb];
                uint32_t a2 = As[r * (KPAD / 2) + kb + 4];
                uint32_t a3 = As[(r + 8) * (KPAD / 2) + kb + 4];
#pragma unroll
                for (int nt = 0; nt < 4; nt++)
                    mma16816(cfr[mt][nt], a0, a1, a2, a3, b[nt][0], b[nt][1]);
            }
        }
    }
}

// ---------------- single-output GEMM (encoder / out-proj with epilogue) ----------------
__global__ __launch_bounds__(256) void gemm_mma_kernel(
    const float* __restrict__ A, const float* __restrict__ W,
    const float* __restrict__ bias, float* __restrict__ C, int M, int flags,
    const float* __restrict__ Xg, const float* __restrict__ skipp)
{
    extern __shared__ __align__(16) char smem[];
    uint32_t* AH = (uint32_t*)smem;
    uint32_t* AL = AH + 128 * (KPAD / 2);
    uint32_t* WH = AL + 128 * (KPAD / 2);
    uint32_t* WL = WH + 128 * (KPAD / 2);
    const int tid = threadIdx.x;
    const int r0 = blockIdx.x * 128;

    convert_A(A, AH, AL, r0, M, tid, (flags & 2) != 0);
    convert_W(W, WH, WL, tid);
    __syncthreads();

    const int w = tid >> 5, lane = tid & 31;
    const int wm = (w & 1) * 64, wn = (w >> 1) * 32;
    const int gr = lane >> 2, qp = lane & 3;

    float cfr[4][4][4];
    mma_core(AH, AL, WH, WL, wm, wn, gr, qp, cfr);

    float g = 0.f;
    if (Xg) g = 1.0f / (1.0f + __expf(-__ldg(skipp)));
#pragma unroll
    for (int mt = 0; mt < 4; mt++) {
#pragma unroll
        for (int half = 0; half < 2; half++) {
            int row = r0 + wm + mt * 16 + gr + half * 8;
            if (row >= M) continue;
#pragma unroll
            for (int nt = 0; nt < 4; nt++) {
                int j = wn + nt * 8 + qp * 2;
                float o0 = cfr[mt][nt][half * 2 + 0] + __ldg(bias + j);
                float o1 = cfr[mt][nt][half * 2 + 1] + __ldg(bias + j + 1);
                if (flags & 1) { o0 = fmaxf(o0, 0.f); o1 = fmaxf(o1, 0.f); }
                if (Xg) {
                    const float2 xv = __ldg((const float2*)(Xg + (size_t)row * CC + j));
                    o0 = g * o0 + (1.f - g) * xv.x;
                    o1 = g * o1 + (1.f - g) * xv.y;
                }
                *(float2*)(C + (size_t)row * CC + j) = make_float2(o0, o1);
            }
        }
    }
}

// ---------------- multi-output GEMM: A resident, loop over up to 5 weight sets ----------
struct Outs5 {
    const float* W[5];
    const float* B[5];
    float*       C[5];
};

__global__ __launch_bounds__(256) void gemm_mma_multi_kernel(
    const float* __restrict__ A, int M, int nw, Outs5 o)
{
    extern __shared__ __align__(16) char smem[];
    uint32_t* AH = (uint32_t*)smem;
    uint32_t* AL = AH + 128 * (KPAD / 2);
    uint32_t* WH = AL + 128 * (KPAD / 2);
    uint32_t* WL = WH + 128 * (KPAD / 2);
    const int tid = threadIdx.x;
    const int r0 = blockIdx.x * 128;

    convert_A(A, AH, AL, r0, M, tid, false);

    const int w = tid >> 5, lane = tid & 31;
    const int wm = (w & 1) * 64, wn = (w >> 1) * 32;
    const int gr = lane >> 2, qp = lane & 3;

    for (int s = 0; s < nw; s++) {
        __syncthreads();               // A stores visible (s=0); prior MMA consumers done (s>0)
        convert_W(o.W[s], WH, WL, tid);
        __syncthreads();

        float cfr[4][4][4];
        mma_core(AH, AL, WH, WL, wm, wn, gr, qp, cfr);

        const float* bias = o.B[s];
        float* C = o.C[s];
#pragma unroll
        for (int mt = 0; mt < 4; mt++) {
#pragma unroll
            for (int half = 0; half < 2; half++) {
                int row = r0 + wm + mt * 16 + gr + half * 8;
                if (row >= M) continue;
#pragma unroll
                for (int nt = 0; nt < 4; nt++) {
                    int j = wn + nt * 8 + qp * 2;
                    float o0 = cfr[mt][nt][half * 2 + 0] + __ldg(bias + j);
                    float o1 = cfr[mt][nt][half * 2 + 1] + __ldg(bias + j + 1);
                    *(float2*)(C + (size_t)row * CC + j) = make_float2(o0, o1);
                }
            }
        }
    }
}

// ---------------- per-edge logits + running segment max ----------------
__global__ void logits_kernel(const int* __restrict__ src, const int* __restrict__ dst,
                              const float* __restrict__ Qd, const float* __restrict__ KRs,
                              const float* __restrict__ prel, float* __restrict__ LG,
                              float* __restrict__ Mx, int nE)
{
    int e = blockIdx.x * (blockDim.x >> 5) + (threadIdx.x >> 5);
    if (e >= nE) return;
    int lane = threadIdx.x & 31;
    int s = __ldg(src + e), d = __ldg(dst + e);
    float4 q = __ldg((const float4*)(Qd + (size_t)d * CC) + lane);
    float4 k = __ldg((const float4*)(KRs + (size_t)s * CC) + lane);
    float p = q.x * k.x + q.y * k.y + q.z * k.z + q.w * k.w;
    p += __shfl_xor_sync(0xffffffffu, p, 1);
    p += __shfl_xor_sync(0xffffffffu, p, 2);
    if ((lane & 3) == 0) {
        int h = lane >> 2;
        float lg = p * __ldg(prel + h) * 0.25f;   // scale = 1/sqrt(16)
        LG[(size_t)e * HH + h] = lg;
        atomicMaxF(Mx + (size_t)d * HH + h, lg);
    }
}

// ---------------- exp + segment sum ----------------
__global__ void expsum_kernel(const int* __restrict__ dst, float* __restrict__ LG,
                              const float* __restrict__ Mx, float* __restrict__ Sm, int nE)
{
    int i = blockIdx.x * blockDim.x + threadIdx.x;
    if (i >= nE * HH) return;
    int e = i >> 3, h = i & 7;
    int d = __ldg(dst + e);
    float ev = __expf(LG[i] - Mx[(size_t)d * HH + h]);
    LG[i] = ev;
    atomicAdd(Sm + (size_t)d * HH + h, ev);
}

// ---------------- alpha * v_r scatter into agg ----------------
__global__ void scatter_kernel(const int* __restrict__ src, const int* __restrict__ dst,
                               const float* __restrict__ LG, const float* __restrict__ Sm,
                               const float* __restrict__ VRs, float* __restrict__ AGGd, int nE)
{
    int e = blockIdx.x * (blockDim.x >> 5) + (threadIdx.x >> 5);
    if (e >= nE) return;
    int lane = threadIdx.x & 31;
    int h = lane >> 2;
    int s = __ldg(src + e), d = __ldg(dst + e);
    float a = __ldg(LG + (size_t)e * HH + h) / (__ldg(Sm + (size_t)d * HH + h) + 1e-16f);
    float4 v = __ldg((const float4*)(VRs + (size_t)s * CC) + lane);
    redAdd4((float*)((float4*)(AGGd + (size_t)d * CC) + lane),
            make_float4(v.x * a, v.y * a, v.z * a, v.w * a));
}

// ---------------- Mx=-inf, Sm=0 init ----------------
__global__ void init_ms_kernel(float* __restrict__ Mx, float* __restrict__ Sm, int n)
{
    int i = blockIdx.x * blockDim.x + threadIdx.x;
    if (i < n) { Mx[i] = __int_as_float(0xff800000); Sm[i] = 0.f; }
}

// ---------------- launcher ----------------
extern "C" void kernel_launch(void* const* d_in, const int* in_sizes, int n_in,
                              void* d_out, int out_size)
{
    const int* tok_stmt = (const int*)d_in[0];
    const int* tok_func = (const int*)d_in[1];
    const int* esrc[3] = {(const int*)d_in[2], (const int*)d_in[4], (const int*)d_in[6]};
    const int* edst[3] = {(const int*)d_in[3], (const int*)d_in[5], (const int*)d_in[7]};
    const float* emb   = (const float*)d_in[8];
    const float* lin_w = (const float*)d_in[9];
    const float* lin_b = (const float*)d_in[10];
    const float* kw = (const float*)d_in[11];
    const float* kb = (const float*)d_in[12];
    const float* qw = (const float*)d_in[13];
    const float* qb = (const float*)d_in[14];
    const float* vw = (const float*)d_in[15];
    const float* vb = (const float*)d_in[16];
    const float* aw = (const float*)d_in[17];
    const float* ab = (const float*)d_in[18];
    const float* skip = (const float*)d_in[19];
    const float* a_rel = (const float*)d_in[20];
    const float* m_rel = (const float*)d_in[21];
    const float* p_rel = (const float*)d_in[22];
    float* out = (float*)d_out;

    float *XA, *XB, *Q, *AGG, *KR0, *VR0, *KR1, *VR1, *KR2, *VR2, *LG, *Mx, *Sm;
    float *WK, *WV, *BK, *BV;
    cudaGetSymbolAddress((void**)&XA, g_XA);
    cudaGetSymbolAddress((void**)&XB, g_XB);
    cudaGetSymbolAddress((void**)&Q,  g_Q);
    cudaGetSymbolAddress((void**)&AGG, g_AGG);
    cudaGetSymbolAddress((void**)&KR0, g_KR0);
    cudaGetSymbolAddress((void**)&VR0, g_VR0);
    cudaGetSymbolAddress((void**)&KR1, g_KR1);
    cudaGetSymbolAddress((void**)&VR1, g_VR1);
    cudaGetSymbolAddress((void**)&KR2, g_KR2);
    cudaGetSymbolAddress((void**)&VR2, g_VR2);
    cudaGetSymbolAddress((void**)&LG, g_LG);
    cudaGetSymbolAddress((void**)&Mx, g_M);
    cudaGetSymbolAddress((void**)&Sm, g_S);
    cudaGetSymbolAddress((void**)&WK, g_WK);
    cudaGetSymbolAddress((void**)&WV, g_WV);
    cudaGetSymbolAddress((void**)&BK, g_BK);
    cudaGetSymbolAddress((void**)&BV, g_BV);

    cudaFuncSetAttribute(gemm_mma_kernel, cudaFuncAttributeMaxDynamicSharedMemorySize, SMEM_GM);
    cudaFuncSetAttribute(gemm_mma_multi_kernel, cudaFuncAttributeMaxDynamicSharedMemorySize, SMEM_GM);

    const int Nt[2] = {NSTMT, NFUNC};
    const size_t base[2] = {0, (size_t)NSTMT * CC};

    // ---- fold a_rel/m_rel into projection weights ----
    combine_kernel<<<NLAYER * 3 * 2, 256>>>(kw, kb, vw, vb, a_rel, m_rel, WK, BK, WV, BV);

    // ---- encoder ----
    encode_kernel<<<(NSTMT + 7) / 8, 256>>>(tok_stmt, emb, AGG, NSTMT);
    encode_kernel<<<(NFUNC + 7) / 8, 256>>>(tok_func, emb, AGG + base[1], NFUNC);
    for (int t = 0; t < 2; t++) {
        int g = (Nt[t] + 127) / 128;
        gemm_mma_kernel<<<g, 256, SMEM_GM>>>(
            AGG + base[t], lin_w + (size_t)t * CC * CC, lin_b + (size_t)t * CC,
            XA + base[t], Nt[t], 1, nullptr, nullptr);
    }

    float* Xcur = XA;
    float* Xnext = XB;

    float* KRr[3] = {KR0, KR1, KR2};
    float* VRr[3] = {VR0, VR1, VR2};

    for (int l = 0; l < NLAYER; l++) {
        // stmt: Q + (KR0, VR0, KR1, VR1) in one multi-GEMM
        {
            Outs5 o;
            o.W[0] = qw + (size_t)(l * 2 + 0) * CC * CC; o.B[0] = qb + (size_t)(l * 2 + 0) * CC; o.C[0] = Q;
            o.W[1] = WK + (size_t)(l * 3 + 0) * CC * CC; o.B[1] = BK + (size_t)(l * 3 + 0) * CC; o.C[1] = KR0;
            o.W[2] = WV + (size_t)(l * 3 + 0) * CC * CC; o.B[2] = BV + (size_t)(l * 3 + 0) * CC; o.C[2] = VR0;
            o.W[3] = WK + (size_t)(l * 3 + 1) * CC * CC; o.B[3] = BK + (size_t)(l * 3 + 1) * CC; o.C[3] = KR1;
            o.W[4] = WV + (size_t)(l * 3 + 1) * CC * CC; o.B[4] = BV + (size_t)(l * 3 + 1) * CC; o.C[4] = VR1;
            gemm_mma_multi_kernel<<<(NSTMT + 127) / 128, 256, SMEM_GM>>>(Xcur, NSTMT, 5, o);
        }
        // func: Q + (KR2, VR2)
        {
            Outs5 o;
            o.W[0] = qw + (size_t)(l * 2 + 1) * CC * CC; o.B[0] = qb + (size_t)(l * 2 + 1) * CC; o.C[0] = Q + base[1];
            o.W[1] = WK + (size_t)(l * 3 + 2) * CC * CC; o.B[1] = BK + (size_t)(l * 3 + 2) * CC; o.C[1] = KR2;
            o.W[2] = WV + (size_t)(l * 3 + 2) * CC * CC; o.B[2] = BV + (size_t)(l * 3 + 2) * CC; o.C[2] = VR2;
            o.W[3] = o.W[0]; o.B[3] = o.B[0]; o.C[3] = Q + base[1];
            o.W[4] = o.W[0]; o.B[4] = o.B[0]; o.C[4] = Q + base[1];
            gemm_mma_multi_kernel<<<(NFUNC + 127) / 128, 256, SMEM_GM>>>(Xcur + base[1], NFUNC, 3, o);
        }
        cudaMemsetAsync(AGG, 0, (size_t)NTOT * CC * sizeof(float));

        for (int r = 0; r < 3; r++) {
            const int dt = (r == 1) ? 1 : 0;
            const int nd = Nt[dt];

            init_ms_kernel<<<(nd * HH + 255) / 256, 256>>>(Mx, Sm, nd * HH);
            logits_kernel<<<(EE + 7) / 8, 256>>>(
                esrc[r], edst[r], Q + base[dt], KRr[r], p_rel + (size_t)(l * 3 + r) * HH, LG, Mx, EE);
            expsum_kernel<<<(EE * HH + 255) / 256, 256>>>(edst[r], LG, Mx, Sm, EE);
            scatter_kernel<<<(EE + 7) / 8, 256>>>(esrc[r], edst[r], LG, Sm, VRr[r], AGG + base[dt], EE);
        }

        // output: fused gelu(A) -> proj -> gated skip epilogue
        float* gate_out = (l == NLAYER - 1) ? out : Xnext;
        for (int t = 0; t < 2; t++) {
            size_t w_off = (size_t)(l * 2 + t) * CC * CC;
            size_t b_off = (size_t)(l * 2 + t) * CC;
            int g = (Nt[t] + 127) / 128;
            gemm_mma_kernel<<<g, 256, SMEM_GM>>>(
                AGG + base[t], aw + w_off, ab + b_off, gate_out + base[t], Nt[t], 2,
                Xcur + base[t], skip + (size_t)(l * 2 + t));
        }
        float* tmp = Xcur; Xcur = Xnext; Xnext = tmp;
    }
}